// round 5
// baseline (speedup 1.0000x reference)
#include <cuda_runtime.h>
#include <math.h>
#include <stdint.h>

// ---------------- problem constants ----------------
#define EM   4      // episode
#define BN_  8      // batch
#define CM   896    // code size
#define HM   448    // lstm hidden per dir
#define KM   512    // memory size
#define G4H  1792   // 4*HM

static const float ALPHAF = 5e-4f;

// ---------------- scratch (__device__ globals; no allocation allowed) ------
__device__ float g_WhhT[2 * 2 * HM * G4H];        // [layer][dir][hp][j]
__device__ float g_X0[BN_ * EM * CM];             // layer0 input  (b*E+t, c)
__device__ float g_X1[BN_ * EM * CM];             // layer0 output / layer1 input
__device__ float g_X2[BN_ * EM * CM];             // layer1 output (zl)
__device__ float g_Gin[2 * BN_ * EM * G4H];       // input projections per dir
__device__ float g_h[2 * BN_ * HM];
__device__ float g_cst[2 * BN_ * HM];
__device__ float g_P1[BN_ * CM * KM];             // 14.7MB
__device__ float g_P2[BN_ * CM * KM];             // 14.7MB
__device__ float g_T1[BN_ * CM * CM];             // 25.7MB
__device__ float g_w[BN_ * KM];
__device__ float g_wU[BN_ * KM];
__device__ float g_cc[BN_ * KM];
__device__ float g_Delta[BN_ * CM];
__device__ float g_klp[BN_];

// ---------------- small helpers ----------------
__device__ __forceinline__ float clampf(float v, float lo, float hi) {
    return fminf(fmaxf(v, lo), hi);
}

// ---------------- tiled transpose with scale:  out[c][r] = s * in[r][c] ----
__global__ void transpose_scale_kernel(const float* __restrict__ in,
                                       float* __restrict__ out,
                                       int rows, int cols, float scale)
{
    __shared__ float tile[32][33];
    size_t boff = (size_t)blockIdx.z * rows * cols;
    in += boff; out += boff;
    int cb = blockIdx.x * 32, rb = blockIdx.y * 32;
    int x = threadIdx.x, y = threadIdx.y;  // (32,8)
#pragma unroll
    for (int i = 0; i < 4; i++) {
        int r = rb + y + i * 8;
        if (r < rows && cb + x < cols)
            tile[y + i * 8][x] = in[(size_t)r * cols + cb + x];
    }
    __syncthreads();
#pragma unroll
    for (int i = 0; i < 4; i++) {
        int ro = cb + y + i * 8;   // indexes the col-dim of input
        int co = rb + x;
        if (ro < cols && co < rows)
            out[(size_t)ro * rows + co] = scale * tile[x][y + i * 8];
    }
}

// ---------------- build X0 from z (E,B,C) -> (b*E+t, c) ----------------
__global__ void build_x0_kernel(const float* __restrict__ z)
{
    int idx = blockIdx.x * blockDim.x + threadIdx.x;
    if (idx >= BN_ * EM * CM) return;
    int c = idx % CM;
    int m = idx / CM;
    int t = m % EM;
    int b = m / EM;
    g_X0[idx] = z[((size_t)t * BN_ + b) * CM + c];
}

// ---------------- init mean / cov ----------------
__global__ void init_mean_kernel(const float* __restrict__ mm, float* __restrict__ mean)
{
    int idx = blockIdx.x * 256 + threadIdx.x;   // [0, KM*CM)
    int b = blockIdx.y;
    mean[(size_t)b * KM * CM + idx] = mm[idx];
}

__global__ void init_cov_kernel(float* __restrict__ cov)
{
    int idx = blockIdx.x * 256 + threadIdx.x;   // [0, KM*KM)
    int b = blockIdx.y;
    int i = idx / KM, j = idx % KM;
    cov[(size_t)b * KM * KM + idx] = (i == j) ? 1.000001f : 0.f;
}

// ---------------- LSTM input projection: Gin[d][m][j] = X[m]·Wih[d][j] + b --
__global__ void inproj_kernel(const float* __restrict__ X,
                              const float* __restrict__ Wih,
                              const float* __restrict__ bias)
{
    int d = blockIdx.y;
    int jb = blockIdx.x * 64;
    __shared__ float Xs[32][33];
    __shared__ float Ws[64][33];
    int tid = threadIdx.x;       // 256
    int tx = tid & 31, ty = tid >> 5;
    float acc[4][2] = {{0.f,0.f},{0.f,0.f},{0.f,0.f},{0.f,0.f}};

    for (int c0 = 0; c0 < CM; c0 += 32) {
#pragma unroll
        for (int i = 0; i < 4; i++) {
            int e = tid + i * 256; int r = e >> 5, cc = e & 31;
            Xs[r][cc] = X[(size_t)r * CM + c0 + cc];
        }
#pragma unroll
        for (int i = 0; i < 8; i++) {
            int e = tid + i * 256; int r = e >> 5, cc = e & 31;
            Ws[r][cc] = Wih[((size_t)d * G4H + jb + r) * CM + c0 + cc];
        }
        __syncthreads();
#pragma unroll
        for (int kk = 0; kk < 32; kk++) {
            float w0 = Ws[tx * 2 + 0][kk];
            float w1 = Ws[tx * 2 + 1][kk];
#pragma unroll
            for (int mi = 0; mi < 4; mi++) {
                float xv = Xs[ty * 4 + mi][kk];
                acc[mi][0] = fmaf(xv, w0, acc[mi][0]);
                acc[mi][1] = fmaf(xv, w1, acc[mi][1]);
            }
        }
        __syncthreads();
    }
#pragma unroll
    for (int mi = 0; mi < 4; mi++)
#pragma unroll
        for (int ji = 0; ji < 2; ji++) {
            int m = ty * 4 + mi;
            int j = jb + tx * 2 + ji;
            g_Gin[((size_t)d * (BN_ * EM) + m) * G4H + j] = acc[mi][ji] + bias[d * G4H + j];
        }
}

// ---------------- LSTM recurrent step (fused gates+update), 448 threads ----
__global__ void lstm_step_kernel(float* __restrict__ Xout, int layer, int step)
{
    int b = blockIdx.x, d = blockIdx.y, tid = threadIdx.x;  // tid in [0,448)
    int t = (d == 0) ? step : (EM - 1 - step);
    __shared__ float hs[HM];
    int hidx = (d * BN_ + b) * HM + tid;
    hs[tid] = (step == 0) ? 0.f : g_h[hidx];
    __syncthreads();

    const float* W = g_WhhT + ((size_t)layer * 2 + d) * HM * G4H;
    float a0 = 0.f, a1 = 0.f, a2 = 0.f, a3 = 0.f;
#pragma unroll 4
    for (int hp = 0; hp < HM; hp++) {
        float hv = hs[hp];
        const float* wr = W + (size_t)hp * G4H + tid;
        a0 = fmaf(wr[0 * HM], hv, a0);
        a1 = fmaf(wr[1 * HM], hv, a1);
        a2 = fmaf(wr[2 * HM], hv, a2);
        a3 = fmaf(wr[3 * HM], hv, a3);
    }
    const float* gi = g_Gin + ((size_t)d * (BN_ * EM) + b * EM + t) * G4H + tid;
    a0 += gi[0 * HM]; a1 += gi[1 * HM]; a2 += gi[2 * HM]; a3 += gi[3 * HM];

    float cp = (step == 0) ? 0.f : g_cst[hidx];
    float si = 1.f / (1.f + expf(-a0));
    float sf = 1.f / (1.f + expf(-a1));
    float so = 1.f / (1.f + expf(-a3));
    float cn = sf * cp + si * tanhf(a2);
    float hn = so * tanhf(cn);
    g_cst[hidx] = cn;
    g_h[hidx] = hn;
    Xout[((size_t)b * EM + t) * CM + d * HM + tid] = hn;
}

// ---------------- SGEMM 128x128x16, 256 threads, 8x8 per thread ----------
// C[M,N] = A[M,Kd] * B[Kd,N]   (all contiguous row-major, batched in z)
// mode==1: C = 2*Pold - A*B   (Pold has shape/stride M*N)
__global__ void __launch_bounds__(256, 2)
sgemm128_kernel(const float* __restrict__ A, const float* __restrict__ B,
                float* __restrict__ C, const float* __restrict__ Pold,
                int M, int N, int Kd, int mode)
{
    __shared__ float As[16][132];
    __shared__ float Bs[16][128];
    int tid = threadIdx.x;
    size_t bz = blockIdx.z;
    A += bz * (size_t)M * Kd;
    B += bz * (size_t)Kd * N;
    C += bz * (size_t)M * N;
    if (mode) Pold += bz * (size_t)M * N;

    int rowBase = blockIdx.y * 128, colBase = blockIdx.x * 128;
    int ar = tid >> 2,      ac4 = (tid & 3) << 2;
    int br = tid >> 5,      bc4 = (tid & 31) << 2;

    const float* Aptr  = A + (size_t)(rowBase + ar) * Kd + ac4;
    const float* Aptr2 = Aptr + (size_t)64 * Kd;
    const float* Bptr  = B + (size_t)br * N + colBase + bc4;
    const float* Bptr2 = Bptr + (size_t)8 * N;

    float4 a0 = *(const float4*)(Aptr);
    float4 a1 = *(const float4*)(Aptr2);
    float4 b0 = *(const float4*)(Bptr);
    float4 b1 = *(const float4*)(Bptr2);

    float acc[8][8];
#pragma unroll
    for (int i = 0; i < 8; i++)
#pragma unroll
        for (int j = 0; j < 8; j++) acc[i][j] = 0.f;

    int tx = (tid & 15) << 3, ty = (tid >> 4) << 3;

    for (int k0 = 0; k0 < Kd; k0 += 16) {
        // store current tiles
        As[ac4 + 0][ar]      = a0.x; As[ac4 + 1][ar]      = a0.y;
        As[ac4 + 2][ar]      = a0.z; As[ac4 + 3][ar]      = a0.w;
        As[ac4 + 0][ar + 64] = a1.x; As[ac4 + 1][ar + 64] = a1.y;
        As[ac4 + 2][ar + 64] = a1.z; As[ac4 + 3][ar + 64] = a1.w;
        *(float4*)&Bs[br][bc4]     = b0;
        *(float4*)&Bs[br + 8][bc4] = b1;
        __syncthreads();

        if (k0 + 16 < Kd) {  // prefetch next
            a0 = *(const float4*)(Aptr + k0 + 16);
            a1 = *(const float4*)(Aptr2 + k0 + 16);
            b0 = *(const float4*)(Bptr + (size_t)(k0 + 16) * N);
            b1 = *(const float4*)(Bptr2 + (size_t)(k0 + 16) * N);
        }
#pragma unroll
        for (int kk = 0; kk < 16; kk++) {
            float ra[8], rb[8];
#pragma unroll
            for (int i = 0; i < 8; i++) ra[i] = As[kk][ty + i];
#pragma unroll
            for (int j = 0; j < 8; j++) rb[j] = Bs[kk][tx + j];
#pragma unroll
            for (int i = 0; i < 8; i++)
#pragma unroll
                for (int j = 0; j < 8; j++)
                    acc[i][j] = fmaf(ra[i], rb[j], acc[i][j]);
        }
        __syncthreads();
    }

#pragma unroll
    for (int i = 0; i < 8; i++) {
        size_t row = (size_t)(rowBase + ty + i);
#pragma unroll
        for (int j = 0; j < 8; j++) {
            size_t idx = row * N + (colBase + tx + j);
            float v = acc[i][j];
            if (mode) v = 2.f * Pold[idx] - v;
            C[idx] = v;
        }
    }
}

// ---------------- w[b][k] = sum_c (zl+0.1*noise)[b][c] * P[b][c][k] --------
__global__ void w_kernel(const float* __restrict__ P,
                         const float* __restrict__ noise, int t)
{
    int b = blockIdx.y;
    int k = blockIdx.x * 256 + threadIdx.x;
    __shared__ float zn[CM];
    const float* zr = g_X2 + ((size_t)b * EM + t) * CM;
    const float* nr = noise + ((size_t)t * BN_ + b) * CM;
    for (int c = threadIdx.x; c < CM; c += 256)
        zn[c] = zr[c] + 0.1f * nr[c];
    __syncthreads();
    const float* Pb = P + (size_t)b * CM * KM + k;
    float acc = 0.f;
#pragma unroll 8
    for (int c = 0; c < CM; c++)
        acc = fmaf(zn[c], Pb[(size_t)c * KM], acc);
    g_w[b * KM + k] = acc;
}

// ------------- Delta[b][c] = zl[b][c] - sum_k w[b][k]*mean[b][k][c] --------
__global__ void delta_kernel(const float* __restrict__ mean, int t)
{
    int b = blockIdx.y;
    int c = blockIdx.x * 128 + threadIdx.x;
    __shared__ float ws[KM];
    for (int i = threadIdx.x; i < KM; i += 128) ws[i] = g_w[b * KM + i];
    __syncthreads();
    const float* mb = mean + (size_t)b * KM * CM + c;
    float acc = 0.f;
#pragma unroll 8
    for (int k = 0; k < KM; k++)
        acc = fmaf(ws[k], mb[(size_t)k * CM], acc);
    g_Delta[b * CM + c] = g_X2[((size_t)b * EM + t) * CM + c] - acc;
}

// ------------- wU[b][j] = sum_k w[b][k]*cov[b][k][j] ----------------------
__global__ void wU_kernel(const float* __restrict__ cov)
{
    int b = blockIdx.y;
    int j = blockIdx.x * 256 + threadIdx.x;
    __shared__ float ws[KM];
    for (int i = threadIdx.x; i < KM; i += 256) ws[i] = g_w[b * KM + i];
    __syncthreads();
    const float* cb = cov + (size_t)b * KM * KM + j;
    float acc = 0.f;
#pragma unroll 8
    for (int k = 0; k < KM; k++)
        acc = fmaf(ws[k], cb[(size_t)k * KM], acc);
    g_wU[b * KM + j] = acc;
}

// ------------- sigma + c = clip(wU/sigma) per batch -----------------------
__global__ void sigma_c_kernel()
{
    int b = blockIdx.x, tid = threadIdx.x;   // 512 threads
    __shared__ float red[512];
    float wv = g_w[b * KM + tid];
    float wu = g_wU[b * KM + tid];
    red[tid] = wv * wu;
    __syncthreads();
    for (int s = 256; s > 0; s >>= 1) {
        if (tid < s) red[tid] += red[tid + s];
        __syncthreads();
    }
    __shared__ float s_sigma;
    if (tid == 0) s_sigma = fmaxf(red[0] + 0.01f, 1e-6f);
    __syncthreads();
    g_cc[b * KM + tid] = clampf(wu / s_sigma, -1000.f, 1000.f);
}

// ------------- mean += c (x) clip(Delta); clip ----------------------------
__global__ void mean_update_kernel(float* __restrict__ mean)
{
    int k = blockIdx.x, b = blockIdx.y;
    float cv = g_cc[b * KM + k];
    size_t base = ((size_t)b * KM + k) * CM;
    for (int c = threadIdx.x; c < CM; c += 128) {
        float dv = clampf(g_Delta[b * CM + c], -100.f, 100.f);
        float m = mean[base + c] + cv * dv;
        mean[base + c] = clampf(m, -1000.f, 1000.f);
    }
}

// ------------- cov update (symmetrized rank-1 + diag clip + EPS) ----------
__global__ void cov_update_kernel(float* __restrict__ cov)
{
    int i = blockIdx.x, b = blockIdx.y;
    float ci = g_cc[b * KM + i];
    float wUi = g_wU[b * KM + i];
    size_t base = ((size_t)b * KM + i) * KM;
    for (int j = threadIdx.x; j < KM; j += 128) {
        float cj = g_cc[b * KM + j];
        float wUj = g_wU[b * KM + j];
        float v = cov[base + j] - 0.5f * (ci * wUj + cj * wUi);
        if (j == i) v = clampf(v, 0.001f, 1000.f) + 1e-6f;
        cov[base + j] = v;
    }
}

// ------------- KL partial per batch ---------------------------------------
__global__ void kl_partial_kernel(const float* __restrict__ mean,
                                  const float* __restrict__ cov,
                                  const float* __restrict__ mm)
{
    int b = blockIdx.x, tid = threadIdx.x;  // 256
    const float pd = 1.0f + 1e-6f;
    const float lpd = logf(pd);
    float s1 = 0.f, s4 = 0.f, s2 = 0.f;

    for (int k = tid; k < KM; k += 256) {
        float q = clampf(cov[((size_t)b * KM + k) * KM + k], 0.001f, 1e6f);
        s1 += clampf(q / pd, 1e-6f, 1000.f);
        s4 += clampf(lpd - logf(q), -10.f, 10.f);
    }
    const float* mb = mean + (size_t)b * KM * CM;
    for (int idx = tid; idx < KM * CM; idx += 256) {
        float d = mb[idx] - mm[idx];
        s2 += fminf(d * d, 1000.f);
    }
    s2 /= pd;

    __shared__ float r1[256], r2[256], r4[256];
    r1[tid] = s1; r2[tid] = s2; r4[tid] = s4;
    __syncthreads();
    for (int s = 128; s > 0; s >>= 1) {
        if (tid < s) { r1[tid] += r1[tid + s]; r2[tid] += r2[tid + s]; r4[tid] += r4[tid + s]; }
        __syncthreads();
    }
    if (tid == 0) {
        float t1 = clampf((float)CM * r1[0], -1e6f, 1e6f);
        float t2 = clampf(r2[0], -1e6f, 1e6f);
        float t4 = clampf((float)CM * r4[0], -1e6f, 1e6f);
        g_klp[b] = t1 + t2 + t4 - (float)(CM * KM);
    }
}

__global__ void kl_final_kernel(float* __restrict__ dkl)
{
    float s = 0.f;
    for (int b = 0; b < BN_; b++) s += g_klp[b];
    dkl[0] = s * (1.0f / BN_);
}

// =========================== host side ====================================
extern "C" void kernel_launch(void* const* d_in, const int* in_sizes, int n_in,
                              void* d_out, int out_size)
{
    const float* z    = (const float*)d_in[0];
    const float* mm   = (const float*)d_in[1];  // memory_mean (K,C)
    const float* nois = (const float*)d_in[2];
    const float* Wih0 = (const float*)d_in[3];
    const float* Whh0 = (const float*)d_in[4];
    const float* b0   = (const float*)d_in[5];
    const float* Wih1 = (const float*)d_in[6];
    const float* Whh1 = (const float*)d_in[7];
    const float* b1   = (const float*)d_in[8];

    float* out_mean = (float*)d_out;                               // (B,K,C)
    float* out_cov  = out_mean + (size_t)BN_ * KM * CM;            // (B,K,K)
    float* out_dkl  = out_cov + (size_t)BN_ * KM * KM;             // scalar

    float *pWhhT, *pX0, *pX1, *pX2, *pP1, *pP2, *pT1;
    cudaGetSymbolAddress((void**)&pWhhT, g_WhhT);
    cudaGetSymbolAddress((void**)&pX0, g_X0);
    cudaGetSymbolAddress((void**)&pX1, g_X1);
    cudaGetSymbolAddress((void**)&pX2, g_X2);
    cudaGetSymbolAddress((void**)&pP1, g_P1);
    cudaGetSymbolAddress((void**)&pP2, g_P2);
    cudaGetSymbolAddress((void**)&pT1, g_T1);

    // --- pre: transpose Whh for both layers; build X0; init mean/cov ---
    transpose_scale_kernel<<<dim3(14, 56, 2), dim3(32, 8)>>>(
        Whh0, pWhhT, G4H, HM, 1.f);
    transpose_scale_kernel<<<dim3(14, 56, 2), dim3(32, 8)>>>(
        Whh1, pWhhT + (size_t)2 * HM * G4H, G4H, HM, 1.f);
    build_x0_kernel<<<(BN_ * EM * CM + 255) / 256, 256>>>(z);
    init_mean_kernel<<<dim3(KM * CM / 256, BN_), 256>>>(mm, out_mean);
    init_cov_kernel<<<dim3(KM * KM / 256, BN_), 256>>>(out_cov);

    // --- bidirectional 2-layer LSTM ---
    // layer 0
    inproj_kernel<<<dim3(G4H / 64, 2), 256>>>(pX0, Wih0, b0);
    for (int s = 0; s < EM; s++)
        lstm_step_kernel<<<dim3(BN_, 2), HM>>>(pX1, 0, s);
    // layer 1
    inproj_kernel<<<dim3(G4H / 64, 2), 256>>>(pX1, Wih1, b1);
    for (int s = 0; s < EM; s++)
        lstm_step_kernel<<<dim3(BN_, 2), HM>>>(pX2, 1, s);

    // --- episodic memory write loop ---
    for (int t = 0; t < EM; t++) {
        // P0 = ALPHA * mean^T   (per batch)
        transpose_scale_kernel<<<dim3(CM / 32, KM / 32, BN_), dim3(32, 8)>>>(
            out_mean, pP1, KM, CM, ALPHAF);

        // 3 Newton-Schulz iterations, ping-pong P1<->P2
        float* Pa = pP1;
        float* Pb = pP2;
        for (int it = 0; it < 3; it++) {
            // T1 = Pa(896x512) @ mean(512x896)
            sgemm128_kernel<<<dim3(CM / 128, CM / 128, BN_), 256>>>(
                Pa, out_mean, pT1, nullptr, CM, CM, KM, 0);
            // Pb = 2*Pa - T1(896x896) @ Pa(896x512)
            sgemm128_kernel<<<dim3(KM / 128, CM / 128, BN_), 256>>>(
                pT1, Pa, Pb, Pa, CM, KM, CM, 1);
            float* tmp = Pa; Pa = Pb; Pb = tmp;
        }
        // final P is in Pa (== pP2 after 3 iters)

        w_kernel<<<dim3(KM / 256, BN_), 256>>>(Pa, nois, t);
        delta_kernel<<<dim3(CM / 128, BN_), 128>>>(out_mean, t);
        wU_kernel<<<dim3(KM / 256, BN_), 256>>>(out_cov);
        sigma_c_kernel<<<BN_, KM>>>();
        mean_update_kernel<<<dim3(KM, BN_), 128>>>(out_mean);
        cov_update_kernel<<<dim3(KM, BN_), 128>>>(out_cov);
    }

    // --- KL ---
    kl_partial_kernel<<<BN_, 256>>>(out_mean, out_cov, mm);
    kl_final_kernel<<<1, 1>>>(out_dkl);
}

// round 6
// speedup vs baseline: 1.4395x; 1.4395x over previous
#include <cuda_runtime.h>
#include <math.h>
#include <stdint.h>

// ---------------- problem constants ----------------
#define EM   4      // episode
#define BN_  8      // batch
#define CM   896    // code size
#define HM   448    // lstm hidden per dir
#define KM   512    // memory size
#define G4H  1792   // 4*HM

static const float ALPHAF = 5e-4f;

// ---------------- scratch (__device__ globals; no allocation allowed) ------
__device__ float g_WhhT[2 * 2 * HM * G4H];        // [layer][dir][hp][j]
__device__ float g_X0[BN_ * EM * CM];             // layer0 input  (b*E+t, c)
__device__ float g_X1[BN_ * EM * CM];             // layer0 output / layer1 input
__device__ float g_X2[BN_ * EM * CM];             // layer1 output (zl)
__device__ float g_Gin[2 * BN_ * EM * G4H];       // input projections per dir
__device__ float g_h[2 * BN_ * HM];
__device__ float g_cst[2 * BN_ * HM];
__device__ float g_P1[BN_ * CM * KM];             // 14.7MB
__device__ float g_P2[BN_ * CM * KM];             // 14.7MB
__device__ float g_Q[BN_ * KM * KM];              // 8.4MB  (Q = mean @ P)
__device__ float g_w[BN_ * KM];
__device__ float g_wU[BN_ * KM];
__device__ float g_cc[BN_ * KM];
__device__ float g_Delta[BN_ * CM];
__device__ float g_klp[BN_];

// ---------------- small helpers ----------------
__device__ __forceinline__ float clampf(float v, float lo, float hi) {
    return fminf(fmaxf(v, lo), hi);
}

// ---------------- tiled transpose with scale:  out[c][r] = s * in[r][c] ----
__global__ void transpose_scale_kernel(const float* __restrict__ in,
                                       float* __restrict__ out,
                                       int rows, int cols, float scale)
{
    __shared__ float tile[32][33];
    size_t boff = (size_t)blockIdx.z * rows * cols;
    in += boff; out += boff;
    int cb = blockIdx.x * 32, rb = blockIdx.y * 32;
    int x = threadIdx.x, y = threadIdx.y;  // (32,8)
#pragma unroll
    for (int i = 0; i < 4; i++) {
        int r = rb + y + i * 8;
        if (r < rows && cb + x < cols)
            tile[y + i * 8][x] = in[(size_t)r * cols + cb + x];
    }
    __syncthreads();
#pragma unroll
    for (int i = 0; i < 4; i++) {
        int ro = cb + y + i * 8;   // indexes the col-dim of input
        int co = rb + x;
        if (ro < cols && co < rows)
            out[(size_t)ro * rows + co] = scale * tile[x][y + i * 8];
    }
}

// ---------------- build X0 from z (E,B,C) -> (b*E+t, c) ----------------
__global__ void build_x0_kernel(const float* __restrict__ z)
{
    int idx = blockIdx.x * blockDim.x + threadIdx.x;
    if (idx >= BN_ * EM * CM) return;
    int c = idx % CM;
    int m = idx / CM;
    int t = m % EM;
    int b = m / EM;
    g_X0[idx] = z[((size_t)t * BN_ + b) * CM + c];
}

// ---------------- init mean / cov ----------------
__global__ void init_mean_kernel(const float* __restrict__ mm, float* __restrict__ mean)
{
    int idx = blockIdx.x * 256 + threadIdx.x;   // [0, KM*CM)
    int b = blockIdx.y;
    mean[(size_t)b * KM * CM + idx] = mm[idx];
}

__global__ void init_cov_kernel(float* __restrict__ cov)
{
    int idx = blockIdx.x * 256 + threadIdx.x;   // [0, KM*KM)
    int b = blockIdx.y;
    int i = idx / KM, j = idx % KM;
    cov[(size_t)b * KM * KM + idx] = (i == j) ? 1.000001f : 0.f;
}

// ---------------- LSTM input projection: Gin[d][m][j] = X[m]·Wih[d][j] + b --
__global__ void inproj_kernel(const float* __restrict__ X,
                              const float* __restrict__ Wih,
                              const float* __restrict__ bias)
{
    int d = blockIdx.y;
    int jb = blockIdx.x * 64;
    __shared__ float Xs[32][33];
    __shared__ float Ws[64][33];
    int tid = threadIdx.x;       // 256
    int tx = tid & 31, ty = tid >> 5;
    float acc[4][2] = {{0.f,0.f},{0.f,0.f},{0.f,0.f},{0.f,0.f}};

    for (int c0 = 0; c0 < CM; c0 += 32) {
#pragma unroll
        for (int i = 0; i < 4; i++) {
            int e = tid + i * 256; int r = e >> 5, cc = e & 31;
            Xs[r][cc] = X[(size_t)r * CM + c0 + cc];
        }
#pragma unroll
        for (int i = 0; i < 8; i++) {
            int e = tid + i * 256; int r = e >> 5, cc = e & 31;
            Ws[r][cc] = Wih[((size_t)d * G4H + jb + r) * CM + c0 + cc];
        }
        __syncthreads();
#pragma unroll
        for (int kk = 0; kk < 32; kk++) {
            float w0 = Ws[tx * 2 + 0][kk];
            float w1 = Ws[tx * 2 + 1][kk];
#pragma unroll
            for (int mi = 0; mi < 4; mi++) {
                float xv = Xs[ty * 4 + mi][kk];
                acc[mi][0] = fmaf(xv, w0, acc[mi][0]);
                acc[mi][1] = fmaf(xv, w1, acc[mi][1]);
            }
        }
        __syncthreads();
    }
#pragma unroll
    for (int mi = 0; mi < 4; mi++)
#pragma unroll
        for (int ji = 0; ji < 2; ji++) {
            int m = ty * 4 + mi;
            int j = jb + tx * 2 + ji;
            g_Gin[((size_t)d * (BN_ * EM) + m) * G4H + j] = acc[mi][ji] + bias[d * G4H + j];
        }
}

// ---------------- LSTM recurrent step (fused gates+update), 448 threads ----
__global__ void lstm_step_kernel(float* __restrict__ Xout, int layer, int step)
{
    int b = blockIdx.x, d = blockIdx.y, tid = threadIdx.x;  // tid in [0,448)
    int t = (d == 0) ? step : (EM - 1 - step);
    __shared__ float hs[HM];
    int hidx = (d * BN_ + b) * HM + tid;
    hs[tid] = (step == 0) ? 0.f : g_h[hidx];
    __syncthreads();

    const float* W = g_WhhT + ((size_t)layer * 2 + d) * HM * G4H;
    float a0 = 0.f, a1 = 0.f, a2 = 0.f, a3 = 0.f;
#pragma unroll 4
    for (int hp = 0; hp < HM; hp++) {
        float hv = hs[hp];
        const float* wr = W + (size_t)hp * G4H + tid;
        a0 = fmaf(wr[0 * HM], hv, a0);
        a1 = fmaf(wr[1 * HM], hv, a1);
        a2 = fmaf(wr[2 * HM], hv, a2);
        a3 = fmaf(wr[3 * HM], hv, a3);
    }
    const float* gi = g_Gin + ((size_t)d * (BN_ * EM) + b * EM + t) * G4H + tid;
    a0 += gi[0 * HM]; a1 += gi[1 * HM]; a2 += gi[2 * HM]; a3 += gi[3 * HM];

    float cp = (step == 0) ? 0.f : g_cst[hidx];
    float si = 1.f / (1.f + expf(-a0));
    float sf = 1.f / (1.f + expf(-a1));
    float so = 1.f / (1.f + expf(-a3));
    float cn = sf * cp + si * tanhf(a2);
    float hn = so * tanhf(cn);
    g_cst[hidx] = cn;
    g_h[hidx] = hn;
    Xout[((size_t)b * EM + t) * CM + d * HM + tid] = hn;
}

// ---------------- SGEMM 128x128x16, 256 threads, 8x8 per thread ----------
// C[M,N] = A[M,Kd] * B[Kd,N]   (all contiguous row-major, batched in z)
// mode==1: C = 2*Pold - A*B   (Pold has shape/stride M*N)
__global__ void __launch_bounds__(256, 2)
sgemm128_kernel(const float* __restrict__ A, const float* __restrict__ B,
                float* __restrict__ C, const float* __restrict__ Pold,
                int M, int N, int Kd, int mode)
{
    __shared__ float As[16][132];
    __shared__ float Bs[16][128];
    int tid = threadIdx.x;
    size_t bz = blockIdx.z;
    A += bz * (size_t)M * Kd;
    B += bz * (size_t)Kd * N;
    C += bz * (size_t)M * N;
    if (mode) Pold += bz * (size_t)M * N;

    int rowBase = blockIdx.y * 128, colBase = blockIdx.x * 128;
    int ar = tid >> 2,      ac4 = (tid & 3) << 2;
    int br = tid >> 5,      bc4 = (tid & 31) << 2;

    const float* Aptr  = A + (size_t)(rowBase + ar) * Kd + ac4;
    const float* Aptr2 = Aptr + (size_t)64 * Kd;
    const float* Bptr  = B + (size_t)br * N + colBase + bc4;
    const float* Bptr2 = Bptr + (size_t)8 * N;

    float4 a0 = *(const float4*)(Aptr);
    float4 a1 = *(const float4*)(Aptr2);
    float4 b0 = *(const float4*)(Bptr);
    float4 b1 = *(const float4*)(Bptr2);

    float acc[8][8];
#pragma unroll
    for (int i = 0; i < 8; i++)
#pragma unroll
        for (int j = 0; j < 8; j++) acc[i][j] = 0.f;

    int tx = (tid & 15) << 3, ty = (tid >> 4) << 3;

    for (int k0 = 0; k0 < Kd; k0 += 16) {
        // store current tiles
        As[ac4 + 0][ar]      = a0.x; As[ac4 + 1][ar]      = a0.y;
        As[ac4 + 2][ar]      = a0.z; As[ac4 + 3][ar]      = a0.w;
        As[ac4 + 0][ar + 64] = a1.x; As[ac4 + 1][ar + 64] = a1.y;
        As[ac4 + 2][ar + 64] = a1.z; As[ac4 + 3][ar + 64] = a1.w;
        *(float4*)&Bs[br][bc4]     = b0;
        *(float4*)&Bs[br + 8][bc4] = b1;
        __syncthreads();

        if (k0 + 16 < Kd) {  // prefetch next
            a0 = *(const float4*)(Aptr + k0 + 16);
            a1 = *(const float4*)(Aptr2 + k0 + 16);
            b0 = *(const float4*)(Bptr + (size_t)(k0 + 16) * N);
            b1 = *(const float4*)(Bptr2 + (size_t)(k0 + 16) * N);
        }
#pragma unroll
        for (int kk = 0; kk < 16; kk++) {
            float ra[8], rb[8];
#pragma unroll
            for (int i = 0; i < 8; i++) ra[i] = As[kk][ty + i];
#pragma unroll
            for (int j = 0; j < 8; j++) rb[j] = Bs[kk][tx + j];
#pragma unroll
            for (int i = 0; i < 8; i++)
#pragma unroll
                for (int j = 0; j < 8; j++)
                    acc[i][j] = fmaf(ra[i], rb[j], acc[i][j]);
        }
        __syncthreads();
    }

#pragma unroll
    for (int i = 0; i < 8; i++) {
        size_t row = (size_t)(rowBase + ty + i);
#pragma unroll
        for (int j = 0; j < 8; j++) {
            size_t idx = row * N + (colBase + tx + j);
            float v = acc[i][j];
            if (mode) v = 2.f * Pold[idx] - v;
            C[idx] = v;
        }
    }
}

// ---------------- w[b][k] = sum_c (zl+0.1*noise)[b][c] * P[b][c][k] --------
__global__ void w_kernel(const float* __restrict__ P,
                         const float* __restrict__ noise, int t)
{
    int b = blockIdx.y;
    int k = blockIdx.x * 256 + threadIdx.x;
    __shared__ float zn[CM];
    const float* zr = g_X2 + ((size_t)b * EM + t) * CM;
    const float* nr = noise + ((size_t)t * BN_ + b) * CM;
    for (int c = threadIdx.x; c < CM; c += 256)
        zn[c] = zr[c] + 0.1f * nr[c];
    __syncthreads();
    const float* Pb = P + (size_t)b * CM * KM + k;
    float acc = 0.f;
#pragma unroll 8
    for (int c = 0; c < CM; c++)
        acc = fmaf(zn[c], Pb[(size_t)c * KM], acc);
    g_w[b * KM + k] = acc;
}

// ------------- Delta[b][c] = zl[b][c] - sum_k w[b][k]*mean[b][k][c] --------
__global__ void delta_kernel(const float* __restrict__ mean, int t)
{
    int b = blockIdx.y;
    int c = blockIdx.x * 128 + threadIdx.x;
    __shared__ float ws[KM];
    for (int i = threadIdx.x; i < KM; i += 128) ws[i] = g_w[b * KM + i];
    __syncthreads();
    const float* mb = mean + (size_t)b * KM * CM + c;
    float acc = 0.f;
#pragma unroll 8
    for (int k = 0; k < KM; k++)
        acc = fmaf(ws[k], mb[(size_t)k * CM], acc);
    g_Delta[b * CM + c] = g_X2[((size_t)b * EM + t) * CM + c] - acc;
}

// ------------- wU[b][j] = sum_k w[b][k]*cov[b][k][j] ----------------------
__global__ void wU_kernel(const float* __restrict__ cov)
{
    int b = blockIdx.y;
    int j = blockIdx.x * 256 + threadIdx.x;
    __shared__ float ws[KM];
    for (int i = threadIdx.x; i < KM; i += 256) ws[i] = g_w[b * KM + i];
    __syncthreads();
    const float* cb = cov + (size_t)b * KM * KM + j;
    float acc = 0.f;
#pragma unroll 8
    for (int k = 0; k < KM; k++)
        acc = fmaf(ws[k], cb[(size_t)k * KM], acc);
    g_wU[b * KM + j] = acc;
}

// ------------- sigma + c = clip(wU/sigma) per batch -----------------------
__global__ void sigma_c_kernel()
{
    int b = blockIdx.x, tid = threadIdx.x;   // 512 threads
    __shared__ float red[512];
    float wv = g_w[b * KM + tid];
    float wu = g_wU[b * KM + tid];
    red[tid] = wv * wu;
    __syncthreads();
    for (int s = 256; s > 0; s >>= 1) {
        if (tid < s) red[tid] += red[tid + s];
        __syncthreads();
    }
    __shared__ float s_sigma;
    if (tid == 0) s_sigma = fmaxf(red[0] + 0.01f, 1e-6f);
    __syncthreads();
    g_cc[b * KM + tid] = clampf(wu / s_sigma, -1000.f, 1000.f);
}

// ------------- mean += c (x) clip(Delta); clip ----------------------------
__global__ void mean_update_kernel(float* __restrict__ mean)
{
    int k = blockIdx.x, b = blockIdx.y;
    float cv = g_cc[b * KM + k];
    size_t base = ((size_t)b * KM + k) * CM;
    for (int c = threadIdx.x; c < CM; c += 128) {
        float dv = clampf(g_Delta[b * CM + c], -100.f, 100.f);
        float m = mean[base + c] + cv * dv;
        mean[base + c] = clampf(m, -1000.f, 1000.f);
    }
}

// ------------- cov update (symmetrized rank-1 + diag clip + EPS) ----------
__global__ void cov_update_kernel(float* __restrict__ cov)
{
    int i = blockIdx.x, b = blockIdx.y;
    float ci = g_cc[b * KM + i];
    float wUi = g_wU[b * KM + i];
    size_t base = ((size_t)b * KM + i) * KM;
    for (int j = threadIdx.x; j < KM; j += 128) {
        float cj = g_cc[b * KM + j];
        float wUj = g_wU[b * KM + j];
        float v = cov[base + j] - 0.5f * (ci * wUj + cj * wUi);
        if (j == i) v = clampf(v, 0.001f, 1000.f) + 1e-6f;
        cov[base + j] = v;
    }
}

// ------------- KL partial per batch ---------------------------------------
__global__ void kl_partial_kernel(const float* __restrict__ mean,
                                  const float* __restrict__ cov,
                                  const float* __restrict__ mm)
{
    int b = blockIdx.x, tid = threadIdx.x;  // 256
    const float pd = 1.0f + 1e-6f;
    const float lpd = logf(pd);
    float s1 = 0.f, s4 = 0.f, s2 = 0.f;

    for (int k = tid; k < KM; k += 256) {
        float q = clampf(cov[((size_t)b * KM + k) * KM + k], 0.001f, 1e6f);
        s1 += clampf(q / pd, 1e-6f, 1000.f);
        s4 += clampf(lpd - logf(q), -10.f, 10.f);
    }
    const float* mb = mean + (size_t)b * KM * CM;
    for (int idx = tid; idx < KM * CM; idx += 256) {
        float d = mb[idx] - mm[idx];
        s2 += fminf(d * d, 1000.f);
    }
    s2 /= pd;

    __shared__ float r1[256], r2[256], r4[256];
    r1[tid] = s1; r2[tid] = s2; r4[tid] = s4;
    __syncthreads();
    for (int s = 128; s > 0; s >>= 1) {
        if (tid < s) { r1[tid] += r1[tid + s]; r2[tid] += r2[tid + s]; r4[tid] += r4[tid + s]; }
        __syncthreads();
    }
    if (tid == 0) {
        float t1 = clampf((float)CM * r1[0], -1e6f, 1e6f);
        float t2 = clampf(r2[0], -1e6f, 1e6f);
        float t4 = clampf((float)CM * r4[0], -1e6f, 1e6f);
        g_klp[b] = t1 + t2 + t4 - (float)(CM * KM);
    }
}

__global__ void kl_final_kernel(float* __restrict__ dkl)
{
    float s = 0.f;
    for (int b = 0; b < BN_; b++) s += g_klp[b];
    dkl[0] = s * (1.0f / BN_);
}

// =========================== host side ====================================
extern "C" void kernel_launch(void* const* d_in, const int* in_sizes, int n_in,
                              void* d_out, int out_size)
{
    const float* z    = (const float*)d_in[0];
    const float* mm   = (const float*)d_in[1];  // memory_mean (K,C)
    const float* nois = (const float*)d_in[2];
    const float* Wih0 = (const float*)d_in[3];
    const float* Whh0 = (const float*)d_in[4];
    const float* b0   = (const float*)d_in[5];
    const float* Wih1 = (const float*)d_in[6];
    const float* Whh1 = (const float*)d_in[7];
    const float* b1   = (const float*)d_in[8];

    float* out_mean = (float*)d_out;                               // (B,K,C)
    float* out_cov  = out_mean + (size_t)BN_ * KM * CM;            // (B,K,K)
    float* out_dkl  = out_cov + (size_t)BN_ * KM * KM;             // scalar

    float *pWhhT, *pX0, *pX1, *pX2, *pP1, *pP2, *pQ;
    cudaGetSymbolAddress((void**)&pWhhT, g_WhhT);
    cudaGetSymbolAddress((void**)&pX0, g_X0);
    cudaGetSymbolAddress((void**)&pX1, g_X1);
    cudaGetSymbolAddress((void**)&pX2, g_X2);
    cudaGetSymbolAddress((void**)&pP1, g_P1);
    cudaGetSymbolAddress((void**)&pP2, g_P2);
    cudaGetSymbolAddress((void**)&pQ,  g_Q);

    // --- pre: transpose Whh for both layers; build X0; init mean/cov ---
    transpose_scale_kernel<<<dim3(14, 56, 2), dim3(32, 8)>>>(
        Whh0, pWhhT, G4H, HM, 1.f);
    transpose_scale_kernel<<<dim3(14, 56, 2), dim3(32, 8)>>>(
        Whh1, pWhhT + (size_t)2 * HM * G4H, G4H, HM, 1.f);
    build_x0_kernel<<<(BN_ * EM * CM + 255) / 256, 256>>>(z);
    init_mean_kernel<<<dim3(KM * CM / 256, BN_), 256>>>(mm, out_mean);
    init_cov_kernel<<<dim3(KM * KM / 256, BN_), 256>>>(out_cov);

    // --- bidirectional 2-layer LSTM ---
    // layer 0
    inproj_kernel<<<dim3(G4H / 64, 2), 256>>>(pX0, Wih0, b0);
    for (int s = 0; s < EM; s++)
        lstm_step_kernel<<<dim3(BN_, 2), HM>>>(pX1, 0, s);
    // layer 1
    inproj_kernel<<<dim3(G4H / 64, 2), 256>>>(pX1, Wih1, b1);
    for (int s = 0; s < EM; s++)
        lstm_step_kernel<<<dim3(BN_, 2), HM>>>(pX2, 1, s);

    // --- episodic memory write loop ---
    for (int t = 0; t < EM; t++) {
        // P0 = ALPHA * mean^T   (per batch)
        transpose_scale_kernel<<<dim3(CM / 32, KM / 32, BN_), dim3(32, 8)>>>(
            out_mean, pP1, KM, CM, ALPHAF);

        // 3 Newton-Schulz iterations, ping-pong P1<->P2.
        // Associativity trick: P' = 2P - P @ (A @ P), with Q = A @ P (KxK)
        // instead of (P @ A) @ P (CxC intermediate): 43% fewer FLOPs.
        float* Pa = pP1;
        float* Pb = pP2;
        for (int it = 0; it < 3; it++) {
            // Q = mean(512x896) @ Pa(896x512)   -> (512x512), Kd=896
            sgemm128_kernel<<<dim3(KM / 128, KM / 128, BN_), 256>>>(
                out_mean, Pa, pQ, nullptr, KM, KM, CM, 0);
            // Pb = 2*Pa - Pa(896x512) @ Q(512x512)
            sgemm128_kernel<<<dim3(KM / 128, CM / 128, BN_), 256>>>(
                Pa, pQ, Pb, Pa, CM, KM, KM, 1);
            float* tmp = Pa; Pa = Pb; Pb = tmp;
        }
        // final P is in Pa (== pP2 after 3 iters)

        w_kernel<<<dim3(KM / 256, BN_), 256>>>(Pa, nois, t);
        delta_kernel<<<dim3(CM / 128, BN_), 128>>>(out_mean, t);
        wU_kernel<<<dim3(KM / 256, BN_), 256>>>(out_cov);
        sigma_c_kernel<<<BN_, KM>>>();
        mean_update_kernel<<<dim3(KM, BN_), 128>>>(out_mean);
        cov_update_kernel<<<dim3(KM, BN_), 128>>>(out_cov);
    }

    // --- KL ---
    kl_partial_kernel<<<BN_, 256>>>(out_mean, out_cov, mm);
    kl_final_kernel<<<1, 1>>>(out_dkl);
}

// round 8
// speedup vs baseline: 2.0797x; 1.4447x over previous
#include <cuda_runtime.h>
#include <cuda_bf16.h>
#include <math.h>
#include <stdint.h>

// ---------------- problem constants ----------------
#define EM   4      // episode
#define BN_  8      // batch
#define CM   896    // code size
#define HM   448    // lstm hidden per dir
#define KM   512    // memory size
#define G4H  1792   // 4*HM

static const float ALPHAF = 5e-4f;

// ---------------- scratch (__device__ globals; no allocation allowed) ------
__device__ float g_WhhT[2 * 2 * HM * G4H];
__device__ float g_X0[BN_ * EM * CM];
__device__ float g_X1[BN_ * EM * CM];
__device__ float g_X2[BN_ * EM * CM];
__device__ float g_Gin[2 * BN_ * EM * G4H];
__device__ float g_h[2 * BN_ * HM];
__device__ float g_cst[2 * BN_ * HM];
__device__ float g_P1[BN_ * CM * KM];             // fp32 P ping
__device__ float g_P2[BN_ * CM * KM];             // fp32 P pong
__device__ float g_Q[BN_ * KM * KM];              // fp32 Q = mean @ P
__device__ float g_w[BN_ * KM];
__device__ float g_wU[BN_ * KM];
__device__ float g_cc[BN_ * KM];
__device__ float g_Delta[BN_ * CM];
__device__ float g_klp[BN_];

// bf16 split operands for tensor-core GEMMs
__device__ __nv_bfloat16 g_mH [BN_ * KM * CM];    // mean hi   (512x896)
__device__ __nv_bfloat16 g_mL [BN_ * KM * CM];    // mean lo
__device__ __nv_bfloat16 g_PaH[BN_ * CM * KM];    // Pa hi     (896x512)
__device__ __nv_bfloat16 g_PaL[BN_ * CM * KM];
__device__ __nv_bfloat16 g_PaTH[BN_ * KM * CM];   // Pa^T hi   (512x896)
__device__ __nv_bfloat16 g_PaTL[BN_ * KM * CM];
__device__ __nv_bfloat16 g_QTH[BN_ * KM * KM];    // Q^T hi    (512x512)
__device__ __nv_bfloat16 g_QTL[BN_ * KM * KM];

// ---------------- small helpers ----------------
__device__ __forceinline__ float clampf(float v, float lo, float hi) {
    return fminf(fmaxf(v, lo), hi);
}
__device__ __forceinline__ uint32_t smem_u32(const void* p) {
    uint32_t a;
    asm("{ .reg .u64 t; cvta.to.shared.u64 t, %1; cvt.u32.u64 %0, t; }"
        : "=r"(a) : "l"(p));
    return a;
}

__device__ __forceinline__ void ldsm_x4(uint32_t* r, uint32_t addr) {
    asm volatile("ldmatrix.sync.aligned.m8n8.x4.shared.b16 {%0,%1,%2,%3}, [%4];"
        : "=r"(r[0]), "=r"(r[1]), "=r"(r[2]), "=r"(r[3]) : "r"(addr));
}

__device__ __forceinline__ void mma16816(float* c, const uint32_t* a,
                                         const uint32_t* b) {
    asm volatile(
        "mma.sync.aligned.m16n8k16.row.col.f32.bf16.bf16.f32 "
        "{%0,%1,%2,%3}, {%4,%5,%6,%7}, {%8,%9}, {%0,%1,%2,%3};"
        : "+f"(c[0]), "+f"(c[1]), "+f"(c[2]), "+f"(c[3])
        : "r"(a[0]), "r"(a[1]), "r"(a[2]), "r"(a[3]), "r"(b[0]), "r"(b[1]));
}

// ==================== bf16x3 tensor-core batched GEMM =====================
// C[M,N] = A(MxKd) @ B^T with BT given (NxKd), both as hi/lo bf16 splits.
// acc = Ah*Bh + Ah*Bl + Al*Bh (fp32 accumulate).  mode==1: C = 2*Pold - acc.
// CTA: 128x128 tile, 256 threads = 8 warps (2 m x 4 n), warp tile 64x32.
// K staged in smem chunks of 64, row stride 72 bf16 (conflict-free ldmatrix).
#define GS 72
#define TILE_ELEMS (128 * GS)
#define GEMM_SMEM  (4 * TILE_ELEMS * 2)   // 73728 bytes

__global__ void __launch_bounds__(256, 1)
gemm_mma_kernel(const __nv_bfloat16* __restrict__ AH,
                const __nv_bfloat16* __restrict__ AL,
                const __nv_bfloat16* __restrict__ BH,
                const __nv_bfloat16* __restrict__ BL,
                float* __restrict__ C, const float* __restrict__ Pold,
                int M, int N, int Kd, int mode)
{
    extern __shared__ __nv_bfloat16 sm[];
    __nv_bfloat16* sAh = sm;
    __nv_bfloat16* sAl = sm + TILE_ELEMS;
    __nv_bfloat16* sBh = sm + 2 * TILE_ELEMS;
    __nv_bfloat16* sBl = sm + 3 * TILE_ELEMS;

    int tid = threadIdx.x, wid = tid >> 5, lane = tid & 31;
    size_t bz = blockIdx.z;
    AH += bz * (size_t)M * Kd;  AL += bz * (size_t)M * Kd;
    BH += bz * (size_t)N * Kd;  BL += bz * (size_t)N * Kd;
    C  += bz * (size_t)M * N;
    if (mode) Pold += bz * (size_t)M * N;

    int rowBase = blockIdx.y * 128, colBase = blockIdx.x * 128;
    int warpRow = (wid >> 2) * 64;       // 0 or 64
    int warpCol = (wid & 3) * 32;        // 0,32,64,96

    float acc[4][4][4];
#pragma unroll
    for (int i = 0; i < 4; i++)
#pragma unroll
        for (int j = 0; j < 4; j++)
#pragma unroll
            for (int q = 0; q < 4; q++) acc[i][j][q] = 0.f;

    // smem u32 bases for ldmatrix
    uint32_t uAh = smem_u32(sAh), uAl = smem_u32(sAl);
    uint32_t uBh = smem_u32(sBh), uBl = smem_u32(sBl);

    for (int k0 = 0; k0 < Kd; k0 += 64) {
        // ---- stage 4 tiles: 128 rows x 64 bf16 each ----
#pragma unroll
        for (int i = 0; i < 4; i++) {
            int e = tid + (i << 8);          // 0..1023
            int r = e >> 3, g = (e & 7) << 3;
            size_t ga = (size_t)(rowBase + r) * Kd + k0 + g;
            size_t gb = (size_t)(colBase + r) * Kd + k0 + g;
            int so = r * GS + g;
            *(uint4*)&sAh[so] = *(const uint4*)&AH[ga];
            *(uint4*)&sAl[so] = *(const uint4*)&AL[ga];
            *(uint4*)&sBh[so] = *(const uint4*)&BH[gb];
            *(uint4*)&sBl[so] = *(const uint4*)&BL[gb];
        }
        __syncthreads();

        // ---- 4 k-steps of 16 ----
#pragma unroll
        for (int ks = 0; ks < 4; ks++) {
            int kk = ks << 4;
            uint32_t ah[4][4], al[4][4], bh[4][2], bl[4][2];
            // A fragments (4 m-tiles of 16)
            int arow = warpRow + (lane & 15);
            int akc  = kk + ((lane >> 4) << 3);
#pragma unroll
            for (int mi = 0; mi < 4; mi++) {
                uint32_t off = (uint32_t)((arow + mi * 16) * GS + akc) * 2;
                ldsm_x4(ah[mi], uAh + off);
                ldsm_x4(al[mi], uAl + off);
            }
            // B fragments (4 n-tiles of 8, loaded 2 at a time via x4)
            int brow = (lane & 7) + (((lane >> 4) & 1) << 3);
            int bkc  = kk + (((lane >> 3) & 1) << 3);
#pragma unroll
            for (int nt = 0; nt < 2; nt++) {
                uint32_t off = (uint32_t)((warpCol + nt * 16 + brow) * GS + bkc) * 2;
                uint32_t rh[4], rl[4];
                ldsm_x4(rh, uBh + off);
                ldsm_x4(rl, uBl + off);
                bh[2 * nt][0] = rh[0]; bh[2 * nt][1] = rh[1];
                bh[2 * nt + 1][0] = rh[2]; bh[2 * nt + 1][1] = rh[3];
                bl[2 * nt][0] = rl[0]; bl[2 * nt][1] = rl[1];
                bl[2 * nt + 1][0] = rl[2]; bl[2 * nt + 1][1] = rl[3];
            }
            // 3-pass split MMA
#pragma unroll
            for (int mi = 0; mi < 4; mi++)
#pragma unroll
                for (int ni = 0; ni < 4; ni++) {
                    mma16816(acc[mi][ni], ah[mi], bh[ni]);
                    mma16816(acc[mi][ni], ah[mi], bl[ni]);
                    mma16816(acc[mi][ni], al[mi], bh[ni]);
                }
        }
        __syncthreads();
    }

    // ---- epilogue: fp32 store, optional 2*Pold - acc ----
    int r0 = rowBase + warpRow + (lane >> 2);
    int c0 = colBase + warpCol + ((lane & 3) << 1);
#pragma unroll
    for (int mi = 0; mi < 4; mi++) {
#pragma unroll
        for (int ni = 0; ni < 4; ni++) {
            float* a = acc[mi][ni];
            size_t i0 = (size_t)(r0 + mi * 16) * N + c0 + ni * 8;
            size_t i1 = i0 + (size_t)8 * N;
            float2 v0 = make_float2(a[0], a[1]);
            float2 v1 = make_float2(a[2], a[3]);
            if (mode) {
                float2 p0 = *(const float2*)(Pold + i0);
                float2 p1 = *(const float2*)(Pold + i1);
                v0.x = 2.f * p0.x - v0.x;  v0.y = 2.f * p0.y - v0.y;
                v1.x = 2.f * p1.x - v1.x;  v1.y = 2.f * p1.y - v1.y;
            }
            *(float2*)(C + i0) = v0;
            *(float2*)(C + i1) = v1;
        }
    }
}

// ----- fused fp32 -> bf16 hi/lo split (normal and/or transposed outputs) --
__global__ void splitboth_kernel(const float* __restrict__ in,
                                 __nv_bfloat16* __restrict__ H,
                                 __nv_bfloat16* __restrict__ L,
                                 __nv_bfloat16* __restrict__ TH,
                                 __nv_bfloat16* __restrict__ TL,
                                 int R, int Cc)
{
    __shared__ float t[32][33];
    size_t bo = (size_t)blockIdx.z * R * Cc;
    int cb = blockIdx.x * 32, rb = blockIdx.y * 32;
    int x = threadIdx.x, y = threadIdx.y;   // (32,8)
#pragma unroll
    for (int i = 0; i < 4; i++) {
        int r = rb + y + i * 8, c = cb + x;
        float v = in[bo + (size_t)r * Cc + c];
        t[y + i * 8][x] = v;
        if (H) {
            __nv_bfloat16 h = __float2bfloat16_rn(v);
            H[bo + (size_t)r * Cc + c] = h;
            L[bo + (size_t)r * Cc + c] =
                __float2bfloat16_rn(v - __bfloat162float(h));
        }
    }
    __syncthreads();
    if (TH) {
#pragma unroll
        for (int i = 0; i < 4; i++) {
            int ro = cb + y + i * 8, co = rb + x;
            float v = t[x][y + i * 8];
            __nv_bfloat16 h = __float2bfloat16_rn(v);
            TH[bo + (size_t)ro * R + co] = h;
            TL[bo + (size_t)ro * R + co] =
                __float2bfloat16_rn(v - __bfloat162float(h));
        }
    }
}

// ---------------- tiled transpose with scale ----------------
__global__ void transpose_scale_kernel(const float* __restrict__ in,
                                       float* __restrict__ out,
                                       int rows, int cols, float scale)
{
    __shared__ float tile[32][33];
    size_t boff = (size_t)blockIdx.z * rows * cols;
    in += boff; out += boff;
    int cb = blockIdx.x * 32, rb = blockIdx.y * 32;
    int x = threadIdx.x, y = threadIdx.y;  // (32,8)
#pragma unroll
    for (int i = 0; i < 4; i++) {
        int r = rb + y + i * 8;
        if (r < rows && cb + x < cols)
            tile[y + i * 8][x] = in[(size_t)r * cols + cb + x];
    }
    __syncthreads();
#pragma unroll
    for (int i = 0; i < 4; i++) {
        int ro = cb + y + i * 8;
        int co = rb + x;
        if (ro < cols && co < rows)
            out[(size_t)ro * rows + co] = scale * tile[x][y + i * 8];
    }
}

// ---------------- build X0 from z (E,B,C) -> (b*E+t, c) ----------------
__global__ void build_x0_kernel(const float* __restrict__ z)
{
    int idx = blockIdx.x * blockDim.x + threadIdx.x;
    if (idx >= BN_ * EM * CM) return;
    int c = idx % CM;
    int m = idx / CM;
    int t = m % EM;
    int b = m / EM;
    g_X0[idx] = z[((size_t)t * BN_ + b) * CM + c];
}

// ---------------- init mean / cov ----------------
__global__ void init_mean_kernel(const float* __restrict__ mm, float* __restrict__ mean)
{
    int idx = blockIdx.x * 256 + threadIdx.x;
    int b = blockIdx.y;
    mean[(size_t)b * KM * CM + idx] = mm[idx];
}

__global__ void init_cov_kernel(float* __restrict__ cov)
{
    int idx = blockIdx.x * 256 + threadIdx.x;
    int b = blockIdx.y;
    int i = idx / KM, j = idx % KM;
    cov[(size_t)b * KM * KM + idx] = (i == j) ? 1.000001f : 0.f;
}

// ---------------- LSTM input projection ----------------
__global__ void inproj_kernel(const float* __restrict__ X,
                              const float* __restrict__ Wih,
                              const float* __restrict__ bias)
{
    int d = blockIdx.y;
    int jb = blockIdx.x * 64;
    __shared__ float Xs[32][33];
    __shared__ float Ws[64][33];
    int tid = threadIdx.x;       // 256
    int tx = tid & 31, ty = tid >> 5;
    float acc[4][2] = {{0.f,0.f},{0.f,0.f},{0.f,0.f},{0.f,0.f}};

    for (int c0 = 0; c0 < CM; c0 += 32) {
#pragma unroll
        for (int i = 0; i < 4; i++) {
            int e = tid + i * 256; int r = e >> 5, cc = e & 31;
            Xs[r][cc] = X[(size_t)r * CM + c0 + cc];
        }
#pragma unroll
        for (int i = 0; i < 8; i++) {
            int e = tid + i * 256; int r = e >> 5, cc = e & 31;
            Ws[r][cc] = Wih[((size_t)d * G4H + jb + r) * CM + c0 + cc];
        }
        __syncthreads();
#pragma unroll
        for (int kk = 0; kk < 32; kk++) {
            float w0 = Ws[tx * 2 + 0][kk];
            float w1 = Ws[tx * 2 + 1][kk];
#pragma unroll
            for (int mi = 0; mi < 4; mi++) {
                float xv = Xs[ty * 4 + mi][kk];
                acc[mi][0] = fmaf(xv, w0, acc[mi][0]);
                acc[mi][1] = fmaf(xv, w1, acc[mi][1]);
            }
        }
        __syncthreads();
    }
#pragma unroll
    for (int mi = 0; mi < 4; mi++)
#pragma unroll
        for (int ji = 0; ji < 2; ji++) {
            int m = ty * 4 + mi;
            int j = jb + tx * 2 + ji;
            g_Gin[((size_t)d * (BN_ * EM) + m) * G4H + j] = acc[mi][ji] + bias[d * G4H + j];
        }
}

// ---------------- LSTM recurrent step ----------------
__global__ void lstm_step_kernel(float* __restrict__ Xout, int layer, int step)
{
    int b = blockIdx.x, d = blockIdx.y, tid = threadIdx.x;
    int t = (d == 0) ? step : (EM - 1 - step);
    __shared__ float hs[HM];
    int hidx = (d * BN_ + b) * HM + tid;
    hs[tid] = (step == 0) ? 0.f : g_h[hidx];
    __syncthreads();

    const float* W = g_WhhT + ((size_t)layer * 2 + d) * HM * G4H;
    float a0 = 0.f, a1 = 0.f, a2 = 0.f, a3 = 0.f;
#pragma unroll 4
    for (int hp = 0; hp < HM; hp++) {
        float hv = hs[hp];
        const float* wr = W + (size_t)hp * G4H + tid;
        a0 = fmaf(wr[0 * HM], hv, a0);
        a1 = fmaf(wr[1 * HM], hv, a1);
        a2 = fmaf(wr[2 * HM], hv, a2);
        a3 = fmaf(wr[3 * HM], hv, a3);
    }
    const float* gi = g_Gin + ((size_t)d * (BN_ * EM) + b * EM + t) * G4H + tid;
    a0 += gi[0 * HM]; a1 += gi[1 * HM]; a2 += gi[2 * HM]; a3 += gi[3 * HM];

    float cp = (step == 0) ? 0.f : g_cst[hidx];
    float si = 1.f / (1.f + expf(-a0));
    float sf = 1.f / (1.f + expf(-a1));
    float so = 1.f / (1.f + expf(-a3));
    float cn = sf * cp + si * tanhf(a2);
    float hn = so * tanhf(cn);
    g_cst[hidx] = cn;
    g_h[hidx] = hn;
    Xout[((size_t)b * EM + t) * CM + d * HM + tid] = hn;
}

// ---------------- w[b][k] = sum_c (zl+0.1*noise)[b][c] * P[b][c][k] --------
__global__ void w_kernel(const float* __restrict__ P,
                         const float* __restrict__ noise, int t)
{
    int b = blockIdx.y;
    int k = blockIdx.x * 256 + threadIdx.x;
    __shared__ float zn[CM];
    const float* zr = g_X2 + ((size_t)b * EM + t) * CM;
    const float* nr = noise + ((size_t)t * BN_ + b) * CM;
    for (int c = threadIdx.x; c < CM; c += 256)
        zn[c] = zr[c] + 0.1f * nr[c];
    __syncthreads();
    const float* Pb = P + (size_t)b * CM * KM + k;
    float acc = 0.f;
#pragma unroll 8
    for (int c = 0; c < CM; c++)
        acc = fmaf(zn[c], Pb[(size_t)c * KM], acc);
    g_w[b * KM + k] = acc;
}

// ------------- Delta[b][c] = zl[b][c] - sum_k w[b][k]*mean[b][k][c] --------
__global__ void delta_kernel(const float* __restrict__ mean, int t)
{
    int b = blockIdx.y;
    int c = blockIdx.x * 128 + threadIdx.x;
    __shared__ float ws[KM];
    for (int i = threadIdx.x; i < KM; i += 128) ws[i] = g_w[b * KM + i];
    __syncthreads();
    const float* mb = mean + (size_t)b * KM * CM + c;
    float acc = 0.f;
#pragma unroll 8
    for (int k = 0; k < KM; k++)
        acc = fmaf(ws[k], mb[(size_t)k * CM], acc);
    g_Delta[b * CM + c] = g_X2[((size_t)b * EM + t) * CM + c] - acc;
}

// ------------- wU[b][j] = sum_k w[b][k]*cov[b][k][j] ----------------------
__global__ void wU_kernel(const float* __restrict__ cov)
{
    int b = blockIdx.y;
    int j = blockIdx.x * 256 + threadIdx.x;
    __shared__ float ws[KM];
    for (int i = threadIdx.x; i < KM; i += 256) ws[i] = g_w[b * KM + i];
    __syncthreads();
    const float* cb = cov + (size_t)b * KM * KM + j;
    float acc = 0.f;
#pragma unroll 8
    for (int k = 0; k < KM; k++)
        acc = fmaf(ws[k], cb[(size_t)k * KM], acc);
    g_wU[b * KM + j] = acc;
}

// ------------- sigma + c = clip(wU/sigma) per batch -----------------------
__global__ void sigma_c_kernel()
{
    int b = blockIdx.x, tid = threadIdx.x;   // 512 threads
    __shared__ float red[512];
    float wv = g_w[b * KM + tid];
    float wu = g_wU[b * KM + tid];
    red[tid] = wv * wu;
    __syncthreads();
    for (int s = 256; s > 0; s >>= 1) {
        if (tid < s) red[tid] += red[tid + s];
        __syncthreads();
    }
    __shared__ float s_sigma;
    if (tid == 0) s_sigma = fmaxf(red[0] + 0.01f, 1e-6f);
    __syncthreads();
    g_cc[b * KM + tid] = clampf(wu / s_sigma, -1000.f, 1000.f);
}

// ------------- mean += c (x) clip(Delta); clip ----------------------------
__global__ void mean_update_kernel(float* __restrict__ mean)
{
    int k = blockIdx.x, b = blockIdx.y;
    float cv = g_cc[b * KM + k];
    size_t base = ((size_t)b * KM + k) * CM;
    for (int c = threadIdx.x; c < CM; c += 128) {
        float dv = clampf(g_Delta[b * CM + c], -100.f, 100.f);
        float m = mean[base + c] + cv * dv;
        mean[base + c] = clampf(m, -1000.f, 1000.f);
    }
}

// ------------- cov update (symmetrized rank-1 + diag clip + EPS) ----------
__global__ void cov_update_kernel(float* __restrict__ cov)
{
    int i = blockIdx.x, b = blockIdx.y;
    float ci = g_cc[b * KM + i];
    float wUi = g_wU[b * KM + i];
    size_t base = ((size_t)b * KM + i) * KM;
    for (int j = threadIdx.x; j < KM; j += 128) {
        float cj = g_cc[b * KM + j];
        float wUj = g_wU[b * KM + j];
        float v = cov[base + j] - 0.5f * (ci * wUj + cj * wUi);
        if (j == i) v = clampf(v, 0.001f, 1000.f) + 1e-6f;
        cov[base + j] = v;
    }
}

// ------------- KL partial per batch ---------------------------------------
__global__ void kl_partial_kernel(const float* __restrict__ mean,
                                  const float* __restrict__ cov,
                                  const float* __restrict__ mm)
{
    int b = blockIdx.x, tid = threadIdx.x;  // 256
    const float pd = 1.0f + 1e-6f;
    const float lpd = logf(pd);
    float s1 = 0.f, s4 = 0.f, s2 = 0.f;

    for (int k = tid; k < KM; k += 256) {
        float q = clampf(cov[((size_t)b * KM + k) * KM + k], 0.001f, 1e6f);
        s1 += clampf(q / pd, 1e-6f, 1000.f);
        s4 += clampf(lpd - logf(q), -10.f, 10.f);
    }
    const float* mb = mean + (size_t)b * KM * CM;
    for (int idx = tid; idx < KM * CM; idx += 256) {
        float d = mb[idx] - mm[idx];
        s2 += fminf(d * d, 1000.f);
    }
    s2 /= pd;

    __shared__ float r1[256], r2[256], r4[256];
    r1[tid] = s1; r2[tid] = s2; r4[tid] = s4;
    __syncthreads();
    for (int s = 128; s > 0; s >>= 1) {
        if (tid < s) { r1[tid] += r1[tid + s]; r2[tid] += r2[tid + s]; r4[tid] += r4[tid + s]; }
        __syncthreads();
    }
    if (tid == 0) {
        float t1 = clampf((float)CM * r1[0], -1e6f, 1e6f);
        float t2 = clampf(r2[0], -1e6f, 1e6f);
        float t4 = clampf((float)CM * r4[0], -1e6f, 1e6f);
        g_klp[b] = t1 + t2 + t4 - (float)(CM * KM);
    }
}

__global__ void kl_final_kernel(float* __restrict__ dkl)
{
    float s = 0.f;
    for (int b = 0; b < BN_; b++) s += g_klp[b];
    dkl[0] = s * (1.0f / BN_);
}

// =========================== host side ====================================
extern "C" void kernel_launch(void* const* d_in, const int* in_sizes, int n_in,
                              void* d_out, int out_size)
{
    const float* z    = (const float*)d_in[0];
    const float* mm   = (const float*)d_in[1];
    const float* nois = (const float*)d_in[2];
    const float* Wih0 = (const float*)d_in[3];
    const float* Whh0 = (const float*)d_in[4];
    const float* b0   = (const float*)d_in[5];
    const float* Wih1 = (const float*)d_in[6];
    const float* Whh1 = (const float*)d_in[7];
    const float* b1   = (const float*)d_in[8];

    float* out_mean = (float*)d_out;                               // (B,K,C)
    float* out_cov  = out_mean + (size_t)BN_ * KM * CM;            // (B,K,K)
    float* out_dkl  = out_cov + (size_t)BN_ * KM * KM;             // scalar

    float *pWhhT, *pX0, *pX1, *pX2, *pP1, *pP2, *pQ;
    cudaGetSymbolAddress((void**)&pWhhT, g_WhhT);
    cudaGetSymbolAddress((void**)&pX0, g_X0);
    cudaGetSymbolAddress((void**)&pX1, g_X1);
    cudaGetSymbolAddress((void**)&pX2, g_X2);
    cudaGetSymbolAddress((void**)&pP1, g_P1);
    cudaGetSymbolAddress((void**)&pP2, g_P2);
    cudaGetSymbolAddress((void**)&pQ,  g_Q);

    __nv_bfloat16 *pmH, *pmL, *pPaH, *pPaL, *pPaTH, *pPaTL, *pQTH, *pQTL;
    cudaGetSymbolAddress((void**)&pmH,   g_mH);
    cudaGetSymbolAddress((void**)&pmL,   g_mL);
    cudaGetSymbolAddress((void**)&pPaH,  g_PaH);
    cudaGetSymbolAddress((void**)&pPaL,  g_PaL);
    cudaGetSymbolAddress((void**)&pPaTH, g_PaTH);
    cudaGetSymbolAddress((void**)&pPaTL, g_PaTL);
    cudaGetSymbolAddress((void**)&pQTH,  g_QTH);
    cudaGetSymbolAddress((void**)&pQTL,  g_QTL);

    cudaFuncSetAttribute(gemm_mma_kernel,
                         cudaFuncAttributeMaxDynamicSharedMemorySize, GEMM_SMEM);

    // --- pre: transpose Whh; build X0; init mean/cov ---
    transpose_scale_kernel<<<dim3(14, 56, 2), dim3(32, 8)>>>(
        Whh0, pWhhT, G4H, HM, 1.f);
    transpose_scale_kernel<<<dim3(14, 56, 2), dim3(32, 8)>>>(
        Whh1, pWhhT + (size_t)2 * HM * G4H, G4H, HM, 1.f);
    build_x0_kernel<<<(BN_ * EM * CM + 255) / 256, 256>>>(z);
    init_mean_kernel<<<dim3(KM * CM / 256, BN_), 256>>>(mm, out_mean);
    init_cov_kernel<<<dim3(KM * KM / 256, BN_), 256>>>(out_cov);

    // --- bidirectional 2-layer LSTM ---
    inproj_kernel<<<dim3(G4H / 64, 2), 256>>>(pX0, Wih0, b0);
    for (int s = 0; s < EM; s++)
        lstm_step_kernel<<<dim3(BN_, 2), HM>>>(pX1, 0, s);
    inproj_kernel<<<dim3(G4H / 64, 2), 256>>>(pX1, Wih1, b1);
    for (int s = 0; s < EM; s++)
        lstm_step_kernel<<<dim3(BN_, 2), HM>>>(pX2, 1, s);

    // --- episodic memory write loop ---
    for (int t = 0; t < EM; t++) {
        // P0 = ALPHA * mean^T (fp32); split mean -> bf16 hi/lo (A of GEMM1)
        transpose_scale_kernel<<<dim3(CM / 32, KM / 32, BN_), dim3(32, 8)>>>(
            out_mean, pP1, KM, CM, ALPHAF);
        splitboth_kernel<<<dim3(CM / 32, KM / 32, BN_), dim3(32, 8)>>>(
            out_mean, pmH, pmL, nullptr, nullptr, KM, CM);

        // 3 Newton-Schulz iterations on tensor cores (bf16x3 split GEMMs)
        float* Pa = pP1;
        float* Pb = pP2;
        for (int it = 0; it < 3; it++) {
            // split Pa -> (PaH/PaL) and transposed (PaTH/PaTL)
            splitboth_kernel<<<dim3(KM / 32, CM / 32, BN_), dim3(32, 8)>>>(
                Pa, pPaH, pPaL, pPaTH, pPaTL, CM, KM);
            // Q = mean(512x896) @ Pa(896x512): A=mean splits, B^T=Pa^T splits
            gemm_mma_kernel<<<dim3(KM / 128, KM / 128, BN_), 256, GEMM_SMEM>>>(
                pmH, pmL, pPaTH, pPaTL, pQ, nullptr, KM, KM, CM, 0);
            // split Q transposed -> QT hi/lo
            splitboth_kernel<<<dim3(KM / 32, KM / 32, BN_), dim3(32, 8)>>>(
                pQ, nullptr, nullptr, pQTH, pQTL, KM, KM);
            // Pb = 2*Pa - Pa(896x512) @ Q(512x512): A=Pa splits, B^T=Q^T splits
            gemm_mma_kernel<<<dim3(KM / 128, CM / 128, BN_), 256, GEMM_SMEM>>>(
                pPaH, pPaL, pQTH, pQTL, Pb, Pa, CM, KM, KM, 1);
            float* tmp = Pa; Pa = Pb; Pb = tmp;
        }
        // final P (fp32) is in Pa

        w_kernel<<<dim3(KM / 256, BN_), 256>>>(Pa, nois, t);
        delta_kernel<<<dim3(CM / 128, BN_), 128>>>(out_mean, t);
        wU_kernel<<<dim3(KM / 256, BN_), 256>>>(out_cov);
        sigma_c_kernel<<<BN_, KM>>>();
        mean_update_kernel<<<dim3(KM, BN_), 128>>>(out_mean);
        cov_update_kernel<<<dim3(KM, BN_), 128>>>(out_cov);
    }

    // --- KL ---
    kl_partial_kernel<<<BN_, 256>>>(out_mean, out_cov, mm);
    kl_final_kernel<<<1, 1>>>(out_dkl);
}

// round 9
// speedup vs baseline: 2.3120x; 1.1117x over previous
#include <cuda_runtime.h>
#include <cuda_bf16.h>
#include <math.h>
#include <stdint.h>

// ---------------- problem constants ----------------
#define EM   4      // episode
#define BN_  8      // batch
#define CM   896    // code size
#define HM   448    // lstm hidden per dir
#define KM   512    // memory size
#define G4H  1792   // 4*HM

static const float ALPHAF = 5e-4f;

// ---------------- scratch (__device__ globals) ----------------
__device__ float g_W4[2 * 2 * HM * G4H];          // [layer][dir][hp][u][gate4]
__device__ float g_X0[BN_ * EM * CM];
__device__ float g_X1[BN_ * EM * CM];
__device__ float g_X2[BN_ * EM * CM];
__device__ float g_Gin[2 * BN_ * EM * G4H];
__device__ float g_h[2 * BN_ * HM];
__device__ float g_cst[2 * BN_ * HM];
__device__ float g_P1[BN_ * CM * KM];             // fp32 P ping
__device__ float g_P2[BN_ * CM * KM];             // fp32 P pong
__device__ float g_w[BN_ * KM];
__device__ float g_wU[BN_ * KM];
__device__ float g_cc[BN_ * KM];
__device__ float g_klp[BN_];

// bf16 split operand buffers
__device__ __nv_bfloat16 g_mH [BN_ * KM * CM];    // mean hi   (512x896)
__device__ __nv_bfloat16 g_mL [BN_ * KM * CM];
__device__ __nv_bfloat16 g_PAh[BN_ * CM * KM];    // P split ping
__device__ __nv_bfloat16 g_PAl[BN_ * CM * KM];
__device__ __nv_bfloat16 g_PBh[BN_ * CM * KM];    // P split pong
__device__ __nv_bfloat16 g_PBl[BN_ * CM * KM];
__device__ __nv_bfloat16 g_QH [BN_ * KM * KM];    // Q split (512x512)
__device__ __nv_bfloat16 g_QL [BN_ * KM * KM];

// ---------------- small helpers ----------------
__device__ __forceinline__ float clampf(float v, float lo, float hi) {
    return fminf(fmaxf(v, lo), hi);
}
__device__ __forceinline__ uint32_t smem_u32(const void* p) {
    uint32_t a;
    asm("{ .reg .u64 t; cvta.to.shared.u64 t, %1; cvt.u32.u64 %0, t; }"
        : "=r"(a) : "l"(p));
    return a;
}
__device__ __forceinline__ void ldsm_x4(uint32_t* r, uint32_t addr) {
    asm volatile("ldmatrix.sync.aligned.m8n8.x4.shared.b16 {%0,%1,%2,%3}, [%4];"
        : "=r"(r[0]), "=r"(r[1]), "=r"(r[2]), "=r"(r[3]) : "r"(addr));
}
__device__ __forceinline__ void ldsm_x4_t(uint32_t* r, uint32_t addr) {
    asm volatile("ldmatrix.sync.aligned.m8n8.x4.trans.shared.b16 {%0,%1,%2,%3}, [%4];"
        : "=r"(r[0]), "=r"(r[1]), "=r"(r[2]), "=r"(r[3]) : "r"(addr));
}
__device__ __forceinline__ void mma16816(float* c, const uint32_t* a,
                                         const uint32_t* b) {
    asm volatile(
        "mma.sync.aligned.m16n8k16.row.col.f32.bf16.bf16.f32 "
        "{%0,%1,%2,%3}, {%4,%5,%6,%7}, {%8,%9}, {%0,%1,%2,%3};"
        : "+f"(c[0]), "+f"(c[1]), "+f"(c[2]), "+f"(c[3])
        : "r"(a[0]), "r"(a[1]), "r"(a[2]), "r"(a[3]), "r"(b[0]), "r"(b[1]));
}

// ==================== bf16x3 tensor-core batched GEMM =====================
// C[M,N] = A(MxKd) @ B(KdxN), A k-contiguous (ldmatrix), B n-contiguous
// (ldmatrix.trans). acc = Ah*Bh + Ah*Bl + Al*Bh, fp32 accumulate.
//   sub:     C_val = 2*Pold - acc  (else C_val = acc)
//   writeC:  store fp32 C
//   writeHL: store bf16 hi/lo split of C_val
// CTA 128x128 tile, 256 thr = 8 warps (2m x 4n), warp tile 64x32, K chunk 64.
#define AS_STRIDE 72
#define BS_STRIDE 136
#define A_TILE (128 * AS_STRIDE)      // 9216 bf16
#define B_TILE (64 * BS_STRIDE)       // 8704 bf16
#define GEMM_SMEM ((2 * A_TILE + 2 * B_TILE) * 2)   // 71680 bytes

__global__ void __launch_bounds__(256, 1)
gemm_mma_kernel(const __nv_bfloat16* __restrict__ AH,
                const __nv_bfloat16* __restrict__ AL,
                const __nv_bfloat16* __restrict__ BH,
                const __nv_bfloat16* __restrict__ BL,
                float* __restrict__ C, const float* __restrict__ Pold,
                __nv_bfloat16* __restrict__ OH, __nv_bfloat16* __restrict__ OL,
                int M, int N, int Kd, int sub, int writeC, int writeHL)
{
    extern __shared__ __nv_bfloat16 sm[];
    __nv_bfloat16* sAh = sm;
    __nv_bfloat16* sAl = sm + A_TILE;
    __nv_bfloat16* sBh = sm + 2 * A_TILE;
    __nv_bfloat16* sBl = sm + 2 * A_TILE + B_TILE;

    int tid = threadIdx.x, wid = tid >> 5, lane = tid & 31;
    size_t bz = blockIdx.z;
    AH += bz * (size_t)M * Kd;  AL += bz * (size_t)M * Kd;
    BH += bz * (size_t)Kd * N;  BL += bz * (size_t)Kd * N;
    size_t cbase = bz * (size_t)M * N;

    int rowBase = blockIdx.y * 128, colBase = blockIdx.x * 128;
    int warpRow = (wid >> 2) * 64;       // 0 or 64
    int warpCol = (wid & 3) * 32;        // 0,32,64,96

    float acc[4][4][4];
#pragma unroll
    for (int i = 0; i < 4; i++)
#pragma unroll
        for (int j = 0; j < 4; j++)
#pragma unroll
            for (int q = 0; q < 4; q++) acc[i][j][q] = 0.f;

    uint32_t uAh = smem_u32(sAh), uAl = smem_u32(sAl);
    uint32_t uBh = smem_u32(sBh), uBl = smem_u32(sBl);

    for (int k0 = 0; k0 < Kd; k0 += 64) {
        // ---- stage A: 128 rows x 64 k ----
#pragma unroll
        for (int i = 0; i < 4; i++) {
            int e = tid + (i << 8);          // 0..1023
            int r = e >> 3, g = (e & 7) << 3;
            size_t ga = (size_t)(rowBase + r) * Kd + k0 + g;
            int so = r * AS_STRIDE + g;
            *(uint4*)&sAh[so] = *(const uint4*)&AH[ga];
            *(uint4*)&sAl[so] = *(const uint4*)&AL[ga];
        }
        // ---- stage B: 64 k-rows x 128 n ----
#pragma unroll
        for (int i = 0; i < 4; i++) {
            int e = tid + (i << 8);          // 0..1023
            int r = e >> 4, g = (e & 15) << 3;
            size_t gb = (size_t)(k0 + r) * N + colBase + g;
            int so = r * BS_STRIDE + g;
            *(uint4*)&sBh[so] = *(const uint4*)&BH[gb];
            *(uint4*)&sBl[so] = *(const uint4*)&BL[gb];
        }
        __syncthreads();

        // ---- 4 k-steps of 16 ----
#pragma unroll
        for (int ks = 0; ks < 4; ks++) {
            int kk = ks << 4;
            uint32_t ah[4][4], al[4][4], bh[4][2], bl[4][2];
            // A fragments (non-trans): 4 m-tiles of 16
            int arow = warpRow + (lane & 15);
            int akc  = kk + ((lane >> 4) << 3);
#pragma unroll
            for (int mi = 0; mi < 4; mi++) {
                uint32_t off = (uint32_t)((arow + mi * 16) * AS_STRIDE + akc) * 2;
                ldsm_x4(ah[mi], uAh + off);
                ldsm_x4(al[mi], uAl + off);
            }
            // B fragments (trans): rows = k, cols = n
            int brow = kk + (lane & 15);
            int bcol = (lane >> 4) << 3;
#pragma unroll
            for (int nt = 0; nt < 2; nt++) {
                uint32_t off = (uint32_t)(brow * BS_STRIDE +
                                          warpCol + nt * 16 + bcol) * 2;
                uint32_t rh[4], rl[4];
                ldsm_x4_t(rh, uBh + off);
                ldsm_x4_t(rl, uBl + off);
                bh[2 * nt][0] = rh[0]; bh[2 * nt][1] = rh[1];
                bh[2 * nt + 1][0] = rh[2]; bh[2 * nt + 1][1] = rh[3];
                bl[2 * nt][0] = rl[0]; bl[2 * nt][1] = rl[1];
                bl[2 * nt + 1][0] = rl[2]; bl[2 * nt + 1][1] = rl[3];
            }
            // 3-pass split MMA
#pragma unroll
            for (int mi = 0; mi < 4; mi++)
#pragma unroll
                for (int ni = 0; ni < 4; ni++) {
                    mma16816(acc[mi][ni], ah[mi], bh[ni]);
                    mma16816(acc[mi][ni], ah[mi], bl[ni]);
                    mma16816(acc[mi][ni], al[mi], bh[ni]);
                }
        }
        __syncthreads();
    }

    // ---- epilogue: optional 2*Pold-acc, fp32 store, fused bf16 split ----
    int r0 = rowBase + warpRow + (lane >> 2);
    int c0 = colBase + warpCol + ((lane & 3) << 1);
#pragma unroll
    for (int mi = 0; mi < 4; mi++) {
#pragma unroll
        for (int ni = 0; ni < 4; ni++) {
            float* a = acc[mi][ni];
            size_t i0 = cbase + (size_t)(r0 + mi * 16) * N + c0 + ni * 8;
            size_t i1 = i0 + (size_t)8 * N;
            float2 v0 = make_float2(a[0], a[1]);
            float2 v1 = make_float2(a[2], a[3]);
            if (sub) {
                float2 p0 = *(const float2*)(Pold + i0);
                float2 p1 = *(const float2*)(Pold + i1);
                v0.x = 2.f * p0.x - v0.x;  v0.y = 2.f * p0.y - v0.y;
                v1.x = 2.f * p1.x - v1.x;  v1.y = 2.f * p1.y - v1.y;
            }
            if (writeC) {
                *(float2*)(C + i0) = v0;
                *(float2*)(C + i1) = v1;
            }
            if (writeHL) {
                __nv_bfloat162 h0, h1, l0, l1;
                h0.x = __float2bfloat16_rn(v0.x);
                h0.y = __float2bfloat16_rn(v0.y);
                h1.x = __float2bfloat16_rn(v1.x);
                h1.y = __float2bfloat16_rn(v1.y);
                l0.x = __float2bfloat16_rn(v0.x - __bfloat162float(h0.x));
                l0.y = __float2bfloat16_rn(v0.y - __bfloat162float(h0.y));
                l1.x = __float2bfloat16_rn(v1.x - __bfloat162float(h1.x));
                l1.y = __float2bfloat16_rn(v1.y - __bfloat162float(h1.y));
                *(__nv_bfloat162*)(OH + i0) = h0;
                *(__nv_bfloat162*)(OH + i1) = h1;
                *(__nv_bfloat162*)(OL + i0) = l0;
                *(__nv_bfloat162*)(OL + i1) = l1;
            }
        }
    }
}

// ----- fused: mean -> (meanH, meanL) + P0 = alpha*mean^T (fp32 + splits) --
__global__ void meansplit_p0_kernel(const float* __restrict__ mean,
                                    __nv_bfloat16* __restrict__ MH,
                                    __nv_bfloat16* __restrict__ ML,
                                    float* __restrict__ P0,
                                    __nv_bfloat16* __restrict__ PH,
                                    __nv_bfloat16* __restrict__ PL)
{
    __shared__ float t[32][33];
    int b = blockIdx.z;
    size_t bm = (size_t)b * KM * CM;
    size_t bp = (size_t)b * CM * KM;
    int cb = blockIdx.x * 32, rb = blockIdx.y * 32;   // rb: K rows, cb: C cols
    int x = threadIdx.x, y = threadIdx.y;             // (32,8)
#pragma unroll
    for (int i = 0; i < 4; i++) {
        int r = rb + y + i * 8, c = cb + x;
        float v = mean[bm + (size_t)r * CM + c];
        t[y + i * 8][x] = v;
        __nv_bfloat16 h = __float2bfloat16_rn(v);
        MH[bm + (size_t)r * CM + c] = h;
        ML[bm + (size_t)r * CM + c] =
            __float2bfloat16_rn(v - __bfloat162float(h));
    }
    __syncthreads();
#pragma unroll
    for (int i = 0; i < 4; i++) {
        int ro = cb + y + i * 8;     // C index
        int co = rb + x;             // K index
        float v = ALPHAF * t[x][y + i * 8];
        size_t idx = bp + (size_t)ro * KM + co;
        P0[idx] = v;
        __nv_bfloat16 h = __float2bfloat16_rn(v);
        PH[idx] = h;
        PL[idx] = __float2bfloat16_rn(v - __bfloat162float(h));
    }
}

// ----- Whh (2,4H,H) -> W4 [dir][hp][u][gate] float4-packed ---------------
__global__ void w4_transpose_kernel(const float* __restrict__ Whh,
                                    float* __restrict__ out)
{
    __shared__ float tile[32][33];
    int d = blockIdx.z;
    size_t bi = (size_t)d * G4H * HM;
    size_t bo = (size_t)d * HM * G4H;
    int cb = blockIdx.x * 32;   // hp
    int rb = blockIdx.y * 32;   // j = gate*HM + u
    int x = threadIdx.x, y = threadIdx.y;
#pragma unroll
    for (int i = 0; i < 4; i++) {
        int r = rb + y + i * 8;
        tile[y + i * 8][x] = Whh[bi + (size_t)r * HM + cb + x];
    }
    __syncthreads();
#pragma unroll
    for (int i = 0; i < 4; i++) {
        int hp = cb + y + i * 8;
        int j  = rb + x;
        int u = j % HM, g = j / HM;
        out[bo + (size_t)hp * G4H + u * 4 + g] = tile[x][y + i * 8];
    }
}

// ---------------- build X0 from z (E,B,C) -> (b*E+t, c) ----------------
__global__ void build_x0_kernel(const float* __restrict__ z)
{
    int idx = blockIdx.x * blockDim.x + threadIdx.x;
    if (idx >= BN_ * EM * CM) return;
    int c = idx % CM;
    int m = idx / CM;
    int t = m % EM;
    int b = m / EM;
    g_X0[idx] = z[((size_t)t * BN_ + b) * CM + c];
}

// ---------------- init mean / cov ----------------
__global__ void init_mean_kernel(const float* __restrict__ mm, float* __restrict__ mean)
{
    int idx = blockIdx.x * 256 + threadIdx.x;
    int b = blockIdx.y;
    mean[(size_t)b * KM * CM + idx] = mm[idx];
}

__global__ void init_cov_kernel(float* __restrict__ cov)
{
    int idx = blockIdx.x * 256 + threadIdx.x;
    int b = blockIdx.y;
    int i = idx / KM, j = idx % KM;
    cov[(size_t)b * KM * KM + idx] = (i == j) ? 1.000001f : 0.f;
}

// ---------------- LSTM input projection ----------------
__global__ void inproj_kernel(const float* __restrict__ X,
                              const float* __restrict__ Wih,
                              const float* __restrict__ bias)
{
    int d = blockIdx.y;
    int jb = blockIdx.x * 64;
    __shared__ float Xs[32][33];
    __shared__ float Ws[64][33];
    int tid = threadIdx.x;       // 256
    int tx = tid & 31, ty = tid >> 5;
    float acc[4][2] = {{0.f,0.f},{0.f,0.f},{0.f,0.f},{0.f,0.f}};

    for (int c0 = 0; c0 < CM; c0 += 32) {
#pragma unroll
        for (int i = 0; i < 4; i++) {
            int e = tid + i * 256; int r = e >> 5, cc = e & 31;
            Xs[r][cc] = X[(size_t)r * CM + c0 + cc];
        }
#pragma unroll
        for (int i = 0; i < 8; i++) {
            int e = tid + i * 256; int r = e >> 5, cc = e & 31;
            Ws[r][cc] = Wih[((size_t)d * G4H + jb + r) * CM + c0 + cc];
        }
        __syncthreads();
#pragma unroll
        for (int kk = 0; kk < 32; kk++) {
            float w0 = Ws[tx * 2 + 0][kk];
            float w1 = Ws[tx * 2 + 1][kk];
#pragma unroll
            for (int mi = 0; mi < 4; mi++) {
                float xv = Xs[ty * 4 + mi][kk];
                acc[mi][0] = fmaf(xv, w0, acc[mi][0]);
                acc[mi][1] = fmaf(xv, w1, acc[mi][1]);
            }
        }
        __syncthreads();
    }
#pragma unroll
    for (int mi = 0; mi < 4; mi++)
#pragma unroll
        for (int ji = 0; ji < 2; ji++) {
            int m = ty * 4 + mi;
            int j = jb + tx * 2 + ji;
            g_Gin[((size_t)d * (BN_ * EM) + m) * G4H + j] = acc[mi][ji] + bias[d * G4H + j];
        }
}

// ---------------- LSTM recurrent step (float4 gate weights) ----------------
__global__ void lstm_step_kernel(float* __restrict__ Xout, int layer, int step)
{
    int b = blockIdx.x, d = blockIdx.y, tid = threadIdx.x;  // tid in [0,448)
    int t = (d == 0) ? step : (EM - 1 - step);
    __shared__ float hs[HM];
    int hidx = (d * BN_ + b) * HM + tid;
    hs[tid] = (step == 0) ? 0.f : g_h[hidx];
    __syncthreads();

    const float* W = g_W4 + ((size_t)layer * 2 + d) * HM * G4H;
    float a0 = 0.f, a1 = 0.f, a2 = 0.f, a3 = 0.f;
#pragma unroll 4
    for (int hp = 0; hp < HM; hp++) {
        float hv = hs[hp];
        float4 wv = ((const float4*)(W + (size_t)hp * G4H))[tid];
        a0 = fmaf(wv.x, hv, a0);
        a1 = fmaf(wv.y, hv, a1);
        a2 = fmaf(wv.z, hv, a2);
        a3 = fmaf(wv.w, hv, a3);
    }
    const float* gi = g_Gin + ((size_t)d * (BN_ * EM) + b * EM + t) * G4H + tid;
    a0 += gi[0 * HM]; a1 += gi[1 * HM]; a2 += gi[2 * HM]; a3 += gi[3 * HM];

    float cp = (step == 0) ? 0.f : g_cst[hidx];
    float si = 1.f / (1.f + expf(-a0));
    float sf = 1.f / (1.f + expf(-a1));
    float so = 1.f / (1.f + expf(-a3));
    float cn = sf * cp + si * tanhf(a2);
    float hn = so * tanhf(cn);
    g_cst[hidx] = cn;
    g_h[hidx] = hn;
    Xout[((size_t)b * EM + t) * CM + d * HM + tid] = hn;
}

// ---------------- w[b][k] = sum_c (zl+0.1*noise)[b][c] * P[b][c][k] --------
__global__ void w_kernel(const float* __restrict__ P,
                         const float* __restrict__ noise, int t)
{
    int b = blockIdx.y;
    int k = blockIdx.x * 256 + threadIdx.x;
    __shared__ float zn[CM];
    const float* zr = g_X2 + ((size_t)b * EM + t) * CM;
    const float* nr = noise + ((size_t)t * BN_ + b) * CM;
    for (int c = threadIdx.x; c < CM; c += 256)
        zn[c] = zr[c] + 0.1f * nr[c];
    __syncthreads();
    const float* Pb = P + (size_t)b * CM * KM + k;
    float acc = 0.f;
#pragma unroll 8
    for (int c = 0; c < CM; c++)
        acc = fmaf(zn[c], Pb[(size_t)c * KM], acc);
    g_w[b * KM + k] = acc;
}

// ------------- wU[b][j] = sum_k w[b][k]*cov[b][k][j] ----------------------
__global__ void wU_kernel(const float* __restrict__ cov)
{
    int b = blockIdx.y;
    int j = blockIdx.x * 256 + threadIdx.x;
    __shared__ float ws[KM];
    for (int i = threadIdx.x; i < KM; i += 256) ws[i] = g_w[b * KM + i];
    __syncthreads();
    const float* cb = cov + (size_t)b * KM * KM + j;
    float acc = 0.f;
#pragma unroll 8
    for (int k = 0; k < KM; k++)
        acc = fmaf(ws[k], cb[(size_t)k * KM], acc);
    g_wU[b * KM + j] = acc;
}

// ------------- sigma + c = clip(wU/sigma) per batch -----------------------
__global__ void sigma_c_kernel()
{
    int b = blockIdx.x, tid = threadIdx.x;   // 512 threads
    __shared__ float red[512];
    float wv = g_w[b * KM + tid];
    float wu = g_wU[b * KM + tid];
    red[tid] = wv * wu;
    __syncthreads();
    for (int s = 256; s > 0; s >>= 1) {
        if (tid < s) red[tid] += red[tid + s];
        __syncthreads();
    }
    __shared__ float s_sigma;
    if (tid == 0) s_sigma = fmaxf(red[0] + 0.01f, 1e-6f);
    __syncthreads();
    g_cc[b * KM + tid] = clampf(wu / s_sigma, -1000.f, 1000.f);
}

// ------------- fused: Delta[b][c] then mean column update -----------------
__global__ void deltaupd_kernel(float* __restrict__ mean, int t)
{
    int b = blockIdx.y;
    int c = blockIdx.x * 128 + threadIdx.x;
    __shared__ float ws[KM];
    __shared__ float cs[KM];
    for (int i = threadIdx.x; i < KM; i += 128) {
        ws[i] = g_w[b * KM + i];
        cs[i] = g_cc[b * KM + i];
    }
    __syncthreads();
    float* mb = mean + (size_t)b * KM * CM + c;
    float acc = 0.f;
#pragma unroll 8
    for (int k = 0; k < KM; k++)
        acc = fmaf(ws[k], mb[(size_t)k * CM], acc);
    float dv = clampf(g_X2[((size_t)b * EM + t) * CM + c] - acc, -100.f, 100.f);
#pragma unroll 4
    for (int k = 0; k < KM; k++) {
        float m = mb[(size_t)k * CM] + cs[k] * dv;
        mb[(size_t)k * CM] = clampf(m, -1000.f, 1000.f);
    }
}

// ------------- cov update (symmetrized rank-1 + diag clip + EPS) ----------
__global__ void cov_update_kernel(float* __restrict__ cov)
{
    int i = blockIdx.x, b = blockIdx.y;
    float ci = g_cc[b * KM + i];
    float wUi = g_wU[b * KM + i];
    size_t base = ((size_t)b * KM + i) * KM;
    for (int j = threadIdx.x; j < KM; j += 128) {
        float cj = g_cc[b * KM + j];
        float wUj = g_wU[b * KM + j];
        float v = cov[base + j] - 0.5f * (ci * wUj + cj * wUi);
        if (j == i) v = clampf(v, 0.001f, 1000.f) + 1e-6f;
        cov[base + j] = v;
    }
}

// ------------- KL partial per batch ---------------------------------------
__global__ void kl_partial_kernel(const float* __restrict__ mean,
                                  const float* __restrict__ cov,
                                  const float* __restrict__ mm)
{
    int b = blockIdx.x, tid = threadIdx.x;  // 256
    const float pd = 1.0f + 1e-6f;
    const float lpd = logf(pd);
    float s1 = 0.f, s4 = 0.f, s2 = 0.f;

    for (int k = tid; k < KM; k += 256) {
        float q = clampf(cov[((size_t)b * KM + k) * KM + k], 0.001f, 1e6f);
        s1 += clampf(q / pd, 1e-6f, 1000.f);
        s4 += clampf(lpd - logf(q), -10.f, 10.f);
    }
    const float* mb = mean + (size_t)b * KM * CM;
    for (int idx = tid; idx < KM * CM; idx += 256) {
        float d = mb[idx] - mm[idx];
        s2 += fminf(d * d, 1000.f);
    }
    s2 /= pd;

    __shared__ float r1[256], r2[256], r4[256];
    r1[tid] = s1; r2[tid] = s2; r4[tid] = s4;
    __syncthreads();
    for (int s = 128; s > 0; s >>= 1) {
        if (tid < s) { r1[tid] += r1[tid + s]; r2[tid] += r2[tid + s]; r4[tid] += r4[tid + s]; }
        __syncthreads();
    }
    if (tid == 0) {
        float t1 = clampf((float)CM * r1[0], -1e6f, 1e6f);
        float t2 = clampf(r2[0], -1e6f, 1e6f);
        float t4 = clampf((float)CM * r4[0], -1e6f, 1e6f);
        g_klp[b] = t1 + t2 + t4 - (float)(CM * KM);
    }
}

__global__ void kl_final_kernel(float* __restrict__ dkl)
{
    float s = 0.f;
    for (int b = 0; b < BN_; b++) s += g_klp[b];
    dkl[0] = s * (1.0f / BN_);
}

// =========================== host side ====================================
extern "C" void kernel_launch(void* const* d_in, const int* in_sizes, int n_in,
                              void* d_out, int out_size)
{
    const float* z    = (const float*)d_in[0];
    const float* mm   = (const float*)d_in[1];
    const float* nois = (const float*)d_in[2];
    const float* Wih0 = (const float*)d_in[3];
    const float* Whh0 = (const float*)d_in[4];
    const float* b0   = (const float*)d_in[5];
    const float* Wih1 = (const float*)d_in[6];
    const float* Whh1 = (const float*)d_in[7];
    const float* b1   = (const float*)d_in[8];

    float* out_mean = (float*)d_out;                               // (B,K,C)
    float* out_cov  = out_mean + (size_t)BN_ * KM * CM;            // (B,K,K)
    float* out_dkl  = out_cov + (size_t)BN_ * KM * KM;             // scalar

    float *pW4, *pX0, *pX1, *pX2, *pP1, *pP2;
    cudaGetSymbolAddress((void**)&pW4, g_W4);
    cudaGetSymbolAddress((void**)&pX0, g_X0);
    cudaGetSymbolAddress((void**)&pX1, g_X1);
    cudaGetSymbolAddress((void**)&pX2, g_X2);
    cudaGetSymbolAddress((void**)&pP1, g_P1);
    cudaGetSymbolAddress((void**)&pP2, g_P2);

    __nv_bfloat16 *pmH, *pmL, *pPAh, *pPAl, *pPBh, *pPBl, *pQH, *pQL;
    cudaGetSymbolAddress((void**)&pmH,  g_mH);
    cudaGetSymbolAddress((void**)&pmL,  g_mL);
    cudaGetSymbolAddress((void**)&pPAh, g_PAh);
    cudaGetSymbolAddress((void**)&pPAl, g_PAl);
    cudaGetSymbolAddress((void**)&pPBh, g_PBh);
    cudaGetSymbolAddress((void**)&pPBl, g_PBl);
    cudaGetSymbolAddress((void**)&pQH,  g_QH);
    cudaGetSymbolAddress((void**)&pQL,  g_QL);

    cudaFuncSetAttribute(gemm_mma_kernel,
                         cudaFuncAttributeMaxDynamicSharedMemorySize, GEMM_SMEM);

    // --- pre: weight repack; build X0; init mean/cov ---
    w4_transpose_kernel<<<dim3(14, 56, 2), dim3(32, 8)>>>(Whh0, pW4);
    w4_transpose_kernel<<<dim3(14, 56, 2), dim3(32, 8)>>>(
        Whh1, pW4 + (size_t)2 * HM * G4H);
    build_x0_kernel<<<(BN_ * EM * CM + 255) / 256, 256>>>(z);
    init_mean_kernel<<<dim3(KM * CM / 256, BN_), 256>>>(mm, out_mean);
    init_cov_kernel<<<dim3(KM * KM / 256, BN_), 256>>>(out_cov);

    // --- bidirectional 2-layer LSTM ---
    inproj_kernel<<<dim3(G4H / 64, 2), 256>>>(pX0, Wih0, b0);
    for (int s = 0; s < EM; s++)
        lstm_step_kernel<<<dim3(BN_, 2), HM>>>(pX1, 0, s);
    inproj_kernel<<<dim3(G4H / 64, 2), 256>>>(pX1, Wih1, b1);
    for (int s = 0; s < EM; s++)
        lstm_step_kernel<<<dim3(BN_, 2), HM>>>(pX2, 1, s);

    // --- episodic memory write loop ---
    for (int t = 0; t < EM; t++) {
        // mean -> meanH/L splits; P0 = alpha*mean^T (fp32 + splits), fused
        meansplit_p0_kernel<<<dim3(CM / 32, KM / 32, BN_), dim3(32, 8)>>>(
            out_mean, pmH, pmL, pP1, pPAh, pPAl);

        float* Pa = pP1;  float* Pb = pP2;
        __nv_bfloat16 *PaH = pPAh, *PaL = pPAl, *PbH = pPBh, *PbL = pPBl;
        for (int it = 0; it < 3; it++) {
            // Q = mean(512x896) @ Pa(896x512) -> QH/QL only (fused split)
            gemm_mma_kernel<<<dim3(KM / 128, KM / 128, BN_), 256, GEMM_SMEM>>>(
                pmH, pmL, PaH, PaL, nullptr, nullptr, pQH, pQL,
                KM, KM, CM, 0, 0, 1);
            // Pb = 2*Pa - Pa(896x512) @ Q(512x512) -> fp32 + splits
            gemm_mma_kernel<<<dim3(KM / 128, CM / 128, BN_), 256, GEMM_SMEM>>>(
                PaH, PaL, pQH, pQL, Pb, Pa, PbH, PbL,
                CM, KM, KM, 1, 1, (it < 2) ? 1 : 0);
            float* tf = Pa; Pa = Pb; Pb = tf;
            __nv_bfloat16* th = PaH; PaH = PbH; PbH = th;
            __nv_bfloat16* tl = PaL; PaL = PbL; PbL = tl;
        }
        // final P (fp32) is in Pa

        w_kernel<<<dim3(KM / 256, BN_), 256>>>(Pa, nois, t);
        wU_kernel<<<dim3(KM / 256, BN_), 256>>>(out_cov);
        sigma_c_kernel<<<BN_, KM>>>();
        deltaupd_kernel<<<dim3(CM / 128, BN_), 128>>>(out_mean, t);
        cov_update_kernel<<<dim3(KM, BN_), 128>>>(out_cov);
    }

    // --- KL ---
    kl_partial_kernel<<<BN_, 256>>>(out_mean, out_cov, mm);
    kl_final_kernel<<<1, 1>>>(out_dkl);
}

// round 12
// speedup vs baseline: 2.3652x; 1.0230x over previous
#include <cuda_runtime.h>
#include <cuda_bf16.h>
#include <math.h>
#include <stdint.h>

// ---------------- problem constants ----------------
#define EM   4      // episode
#define BN_  8      // batch
#define CM   896    // code size
#define HM   448    // lstm hidden per dir
#define KM   512    // memory size
#define G4H  1792   // 4*HM

static const float ALPHAF = 5e-4f;

// ---------------- scratch (__device__ globals) ----------------
__device__ float g_W4[2 * 2 * HM * G4H];          // [layer][dir][hp][u][gate4]
__device__ float g_X0[BN_ * EM * CM];
__device__ float g_X1[BN_ * EM * CM];
__device__ float g_X2[BN_ * EM * CM];
__device__ float g_Gin[2 * BN_ * EM * G4H];
__device__ float g_h[2 * BN_ * HM];
__device__ float g_cst[2 * BN_ * HM];
__device__ float g_P1[BN_ * CM * KM];             // fp32 P ping
__device__ float g_P2[BN_ * CM * KM];             // fp32 P pong
__device__ float g_w[BN_ * KM];
__device__ float g_wU[BN_ * KM];
__device__ float g_cc[BN_ * KM];
__device__ float g_klp[BN_];

// bf16 split operand buffers
__device__ __nv_bfloat16 g_mH [BN_ * KM * CM];    // mean hi   (512x896)
__device__ __nv_bfloat16 g_mL [BN_ * KM * CM];
__device__ __nv_bfloat16 g_PAh[BN_ * CM * KM];    // P split ping
__device__ __nv_bfloat16 g_PAl[BN_ * CM * KM];
__device__ __nv_bfloat16 g_PBh[BN_ * CM * KM];    // P split pong
__device__ __nv_bfloat16 g_PBl[BN_ * CM * KM];
__device__ __nv_bfloat16 g_QH [BN_ * KM * KM];    // Q split (512x512)
__device__ __nv_bfloat16 g_QL [BN_ * KM * KM];

// ---------------- small helpers ----------------
__device__ __forceinline__ float clampf(float v, float lo, float hi) {
    return fminf(fmaxf(v, lo), hi);
}
__device__ __forceinline__ uint32_t smem_u32(const void* p) {
    uint32_t a;
    asm("{ .reg .u64 t; cvta.to.shared.u64 t, %1; cvt.u32.u64 %0, t; }"
        : "=r"(a) : "l"(p));
    return a;
}
__device__ __forceinline__ void ldsm_x4(uint32_t* r, uint32_t addr) {
    asm volatile("ldmatrix.sync.aligned.m8n8.x4.shared.b16 {%0,%1,%2,%3}, [%4];"
        : "=r"(r[0]), "=r"(r[1]), "=r"(r[2]), "=r"(r[3]) : "r"(addr));
}
__device__ __forceinline__ void ldsm_x4_t(uint32_t* r, uint32_t addr) {
    asm volatile("ldmatrix.sync.aligned.m8n8.x4.trans.shared.b16 {%0,%1,%2,%3}, [%4];"
        : "=r"(r[0]), "=r"(r[1]), "=r"(r[2]), "=r"(r[3]) : "r"(addr));
}
__device__ __forceinline__ void mma16816(float* c, const uint32_t* a,
                                         const uint32_t* b) {
    asm volatile(
        "mma.sync.aligned.m16n8k16.row.col.f32.bf16.bf16.f32 "
        "{%0,%1,%2,%3}, {%4,%5,%6,%7}, {%8,%9}, {%0,%1,%2,%3};"
        : "+f"(c[0]), "+f"(c[1]), "+f"(c[2]), "+f"(c[3])
        : "r"(a[0]), "r"(a[1]), "r"(a[2]), "r"(a[3]), "r"(b[0]), "r"(b[1]));
}
__device__ __forceinline__ void cp16(uint32_t dst, const void* src) {
    asm volatile("cp.async.cg.shared.global [%0], [%1], 16;"
        :: "r"(dst), "l"(src));
}
#define CP_COMMIT()  asm volatile("cp.async.commit_group;" ::: "memory")
#define CP_WAIT1()   asm volatile("cp.async.wait_group 1;" ::: "memory")
#define CP_WAIT0()   asm volatile("cp.async.wait_group 0;" ::: "memory")

// ==================== bf16x3 tensor-core batched GEMM =====================
// C[M,N] = A(MxKd) @ B(KdxN), A k-contiguous (ldmatrix), B n-contiguous
// (ldmatrix.trans). acc = Ah*Bh + Ah*Bl + Al*Bh, fp32 accumulate.
// cp.async 2-stage double-buffered K pipeline (chunk = 64).
//   sub: C_val = 2*Pold - acc; writeC: store fp32; writeHL: store bf16 split.
#define AS_STRIDE 72
#define BS_STRIDE 136
#define A_TILE (128 * AS_STRIDE)      // 9216 bf16
#define B_TILE (64 * BS_STRIDE)       // 8704 bf16
#define STAGE_ELEMS (2 * A_TILE + 2 * B_TILE)        // 35840 bf16
#define GEMM_SMEM (2 * STAGE_ELEMS * 2)              // 143360 bytes

__global__ void __launch_bounds__(256, 1)
gemm_mma_kernel(const __nv_bfloat16* __restrict__ AH,
                const __nv_bfloat16* __restrict__ AL,
                const __nv_bfloat16* __restrict__ BH,
                const __nv_bfloat16* __restrict__ BL,
                float* __restrict__ C, const float* __restrict__ Pold,
                __nv_bfloat16* __restrict__ OH, __nv_bfloat16* __restrict__ OL,
                int M, int N, int Kd, int sub, int writeC, int writeHL)
{
    extern __shared__ __nv_bfloat16 sm[];
    int tid = threadIdx.x, wid = tid >> 5, lane = tid & 31;
    size_t bz = blockIdx.z;
    AH += bz * (size_t)M * Kd;  AL += bz * (size_t)M * Kd;
    BH += bz * (size_t)Kd * N;  BL += bz * (size_t)Kd * N;
    size_t cbase = bz * (size_t)M * N;

    int rowBase = blockIdx.y * 128, colBase = blockIdx.x * 128;
    int warpRow = (wid >> 2) * 64;       // 0 or 64
    int warpCol = (wid & 3) * 32;        // 0,32,64,96

    float acc[4][4][4];
#pragma unroll
    for (int i = 0; i < 4; i++)
#pragma unroll
        for (int j = 0; j < 4; j++)
#pragma unroll
            for (int q = 0; q < 4; q++) acc[i][j][q] = 0.f;

    uint32_t uSm = smem_u32(sm);

    int nch = Kd >> 6;

#define STAGE_CHUNK(cidx, sslot) do {                                        \
        uint32_t ub = uSm + (uint32_t)(sslot) * (STAGE_ELEMS * 2);           \
        uint32_t uAh_ = ub, uAl_ = ub + A_TILE * 2;                          \
        uint32_t uBh_ = ub + 2 * A_TILE * 2, uBl_ = uBh_ + B_TILE * 2;       \
        int k0_ = (cidx) << 6;                                               \
        _Pragma("unroll")                                                    \
        for (int i = 0; i < 4; i++) {                                        \
            int e = tid + (i << 8);                                          \
            int r = e >> 3, g = (e & 7) << 3;                                \
            size_t ga = (size_t)(rowBase + r) * Kd + k0_ + g;                \
            uint32_t so = (uint32_t)(r * AS_STRIDE + g) * 2;                 \
            cp16(uAh_ + so, AH + ga);                                        \
            cp16(uAl_ + so, AL + ga);                                        \
        }                                                                    \
        _Pragma("unroll")                                                    \
        for (int i = 0; i < 4; i++) {                                        \
            int e = tid + (i << 8);                                          \
            int r = e >> 4, g = (e & 15) << 3;                               \
            size_t gb = (size_t)(k0_ + r) * N + colBase + g;                 \
            uint32_t so = (uint32_t)(r * BS_STRIDE + g) * 2;                 \
            cp16(uBh_ + so, BH + gb);                                        \
            cp16(uBl_ + so, BL + gb);                                        \
        }                                                                    \
    } while (0)

    // prologue: chunk 0 into slot 0
    STAGE_CHUNK(0, 0);
    CP_COMMIT();

    for (int c = 0; c < nch; c++) {
        if (c + 1 < nch) {
            STAGE_CHUNK(c + 1, (c + 1) & 1);
            CP_COMMIT();
            CP_WAIT1();
        } else {
            CP_WAIT0();
        }
        __syncthreads();

        uint32_t ub = uSm + (uint32_t)(c & 1) * (STAGE_ELEMS * 2);
        uint32_t uAh = ub, uAl = ub + A_TILE * 2;
        uint32_t uBh = ub + 2 * A_TILE * 2, uBl = uBh + B_TILE * 2;

        // ---- 4 k-steps of 16 ----
#pragma unroll
        for (int ks = 0; ks < 4; ks++) {
            int kk = ks << 4;
            uint32_t ah[4][4], al[4][4], bh[4][2], bl[4][2];
            // A fragments (non-trans): 4 m-tiles of 16
            int arow = warpRow + (lane & 15);
            int akc  = kk + ((lane >> 4) << 3);
#pragma unroll
            for (int mi = 0; mi < 4; mi++) {
                uint32_t off = (uint32_t)((arow + mi * 16) * AS_STRIDE + akc) * 2;
                ldsm_x4(ah[mi], uAh + off);
                ldsm_x4(al[mi], uAl + off);
            }
            // B fragments (trans): rows = k, cols = n
            int brow = kk + (lane & 15);
            int bcol = (lane >> 4) << 3;
#pragma unroll
            for (int nt = 0; nt < 2; nt++) {
                uint32_t off = (uint32_t)(brow * BS_STRIDE +
                                          warpCol + nt * 16 + bcol) * 2;
                uint32_t rh[4], rl[4];
                ldsm_x4_t(rh, uBh + off);
                ldsm_x4_t(rl, uBl + off);
                bh[2 * nt][0] = rh[0]; bh[2 * nt][1] = rh[1];
                bh[2 * nt + 1][0] = rh[2]; bh[2 * nt + 1][1] = rh[3];
                bl[2 * nt][0] = rl[0]; bl[2 * nt][1] = rl[1];
                bl[2 * nt + 1][0] = rl[2]; bl[2 * nt + 1][1] = rl[3];
            }
            // 3-pass split MMA
#pragma unroll
            for (int mi = 0; mi < 4; mi++)
#pragma unroll
                for (int ni = 0; ni < 4; ni++) {
                    mma16816(acc[mi][ni], ah[mi], bh[ni]);
                    mma16816(acc[mi][ni], ah[mi], bl[ni]);
                    mma16816(acc[mi][ni], al[mi], bh[ni]);
                }
        }
        __syncthreads();
    }
#undef STAGE_CHUNK

    // ---- epilogue: optional 2*Pold-acc, fp32 store, fused bf16 split ----
    int r0 = rowBase + warpRow + (lane >> 2);
    int c0 = colBase + warpCol + ((lane & 3) << 1);
#pragma unroll
    for (int mi = 0; mi < 4; mi++) {
#pragma unroll
        for (int ni = 0; ni < 4; ni++) {
            float* a = acc[mi][ni];
            size_t i0 = cbase + (size_t)(r0 + mi * 16) * N + c0 + ni * 8;
            size_t i1 = i0 + (size_t)8 * N;
            float2 v0 = make_float2(a[0], a[1]);
            float2 v1 = make_float2(a[2], a[3]);
            if (sub) {
                float2 p0 = *(const float2*)(Pold + i0);
                float2 p1 = *(const float2*)(Pold + i1);
                v0.x = 2.f * p0.x - v0.x;  v0.y = 2.f * p0.y - v0.y;
                v1.x = 2.f * p1.x - v1.x;  v1.y = 2.f * p1.y - v1.y;
            }
            if (writeC) {
                *(float2*)(C + i0) = v0;
                *(float2*)(C + i1) = v1;
            }
            if (writeHL) {
                __nv_bfloat162 h0, h1, l0, l1;
                h0.x = __float2bfloat16_rn(v0.x);
                h0.y = __float2bfloat16_rn(v0.y);
                h1.x = __float2bfloat16_rn(v1.x);
                h1.y = __float2bfloat16_rn(v1.y);
                l0.x = __float2bfloat16_rn(v0.x - __bfloat162float(h0.x));
                l0.y = __float2bfloat16_rn(v0.y - __bfloat162float(h0.y));
                l1.x = __float2bfloat16_rn(v1.x - __bfloat162float(h1.x));
                l1.y = __float2bfloat16_rn(v1.y - __bfloat162float(h1.y));
                *(__nv_bfloat162*)(OH + i0) = h0;
                *(__nv_bfloat162*)(OH + i1) = h1;
                *(__nv_bfloat162*)(OL + i0) = l0;
                *(__nv_bfloat162*)(OL + i1) = l1;
            }
        }
    }
}

// ----- fused: mean -> (meanH, meanL) + P0 = alpha*mean^T (fp32 + splits) --
__global__ void meansplit_p0_kernel(const float* __restrict__ mean,
                                    __nv_bfloat16* __restrict__ MH,
                                    __nv_bfloat16* __restrict__ ML,
                                    float* __restrict__ P0,
                                    __nv_bfloat16* __restrict__ PH,
                                    __nv_bfloat16* __restrict__ PL)
{
    __shared__ float t[32][33];
    int b = blockIdx.z;
    size_t bm = (size_t)b * KM * CM;
    size_t bp = (size_t)b * CM * KM;
    int cb = blockIdx.x * 32, rb = blockIdx.y * 32;   // rb: K rows, cb: C cols
    int x = threadIdx.x, y = threadIdx.y;             // (32,8)
#pragma unroll
    for (int i = 0; i < 4; i++) {
        int r = rb + y + i * 8, c = cb + x;
        float v = mean[bm + (size_t)r * CM + c];
        t[y + i * 8][x] = v;
        __nv_bfloat16 h = __float2bfloat16_rn(v);
        MH[bm + (size_t)r * CM + c] = h;
        ML[bm + (size_t)r * CM + c] =
            __float2bfloat16_rn(v - __bfloat162float(h));
    }
    __syncthreads();
#pragma unroll
    for (int i = 0; i < 4; i++) {
        int ro = cb + y + i * 8;     // C index
        int co = rb + x;             // K index
        float v = ALPHAF * t[x][y + i * 8];
        size_t idx = bp + (size_t)ro * KM + co;
        P0[idx] = v;
        __nv_bfloat16 h = __float2bfloat16_rn(v);
        PH[idx] = h;
        PL[idx] = __float2bfloat16_rn(v - __bfloat162float(h));
    }
}

// ----- Whh (2,4H,H) -> W4 [dir][hp][u][gate] float4-packed ---------------
__global__ void w4_transpose_kernel(const float* __restrict__ Whh,
                                    float* __restrict__ out)
{
    __shared__ float tile[32][33];
    int d = blockIdx.z;
    size_t bi = (size_t)d * G4H * HM;
    size_t bo = (size_t)d * HM * G4H;
    int cb = blockIdx.x * 32;   // hp
    int rb = blockIdx.y * 32;   // j = gate*HM + u
    int x = threadIdx.x, y = threadIdx.y;
#pragma unroll
    for (int i = 0; i < 4; i++) {
        int r = rb + y + i * 8;
        tile[y + i * 8][x] = Whh[bi + (size_t)r * HM + cb + x];
    }
    __syncthreads();
#pragma unroll
    for (int i = 0; i < 4; i++) {
        int hp = cb + y + i * 8;
        int j  = rb + x;
        int u = j % HM, g = j / HM;
        out[bo + (size_t)hp * G4H + u * 4 + g] = tile[x][y + i * 8];
    }
}

// ---------------- build X0 from z (E,B,C) -> (b*E+t, c) ----------------
__global__ void build_x0_kernel(const float* __restrict__ z)
{
    int idx = blockIdx.x * blockDim.x + threadIdx.x;
    if (idx >= BN_ * EM * CM) return;
    int c = idx % CM;
    int m = idx / CM;
    int t = m % EM;
    int b = m / EM;
    g_X0[idx] = z[((size_t)t * BN_ + b) * CM + c];
}

// ---------------- init mean / cov ----------------
__global__ void init_mean_kernel(const float* __restrict__ mm, float* __restrict__ mean)
{
    int idx = blockIdx.x * 256 + threadIdx.x;
    int b = blockIdx.y;
    mean[(size_t)b * KM * CM + idx] = mm[idx];
}

__global__ void init_cov_kernel(float* __restrict__ cov)
{
    int idx = blockIdx.x * 256 + threadIdx.x;
    int b = blockIdx.y;
    int i = idx / KM, j = idx % KM;
    cov[(size_t)b * KM * KM + idx] = (i == j) ? 1.000001f : 0.f;
}

// ---------------- LSTM input projection ----------------
__global__ void inproj_kernel(const float* __restrict__ X,
                              const float* __restrict__ Wih,
                              const float* __restrict__ bias)
{
    int d = blockIdx.y;
    int jb = blockIdx.x * 64;
    __shared__ float Xs[32][33];
    __shared__ float Ws[64][33];
    int tid = threadIdx.x;       // 256
    int tx = tid & 31, ty = tid >> 5;
    float acc[4][2] = {{0.f,0.f},{0.f,0.f},{0.f,0.f},{0.f,0.f}};

    for (int c0 = 0; c0 < CM; c0 += 32) {
#pragma unroll
        for (int i = 0; i < 4; i++) {
            int e = tid + i * 256; int r = e >> 5, cc = e & 31;
            Xs[r][cc] = X[(size_t)r * CM + c0 + cc];
        }
#pragma unroll
        for (int i = 0; i < 8; i++) {
            int e = tid + i * 256; int r = e >> 5, cc = e & 31;
            Ws[r][cc] = Wih[((size_t)d * G4H + jb + r) * CM + c0 + cc];
        }
        __syncthreads();
#pragma unroll
        for (int kk = 0; kk < 32; kk++) {
            float w0 = Ws[tx * 2 + 0][kk];
            float w1 = Ws[tx * 2 + 1][kk];
#pragma unroll
            for (int mi = 0; mi < 4; mi++) {
                float xv = Xs[ty * 4 + mi][kk];
                acc[mi][0] = fmaf(xv, w0, acc[mi][0]);
                acc[mi][1] = fmaf(xv, w1, acc[mi][1]);
            }
        }
        __syncthreads();
    }
#pragma unroll
    for (int mi = 0; mi < 4; mi++)
#pragma unroll
        for (int ji = 0; ji < 2; ji++) {
            int m = ty * 4 + mi;
            int j = jb + tx * 2 + ji;
            g_Gin[((size_t)d * (BN_ * EM) + m) * G4H + j] = acc[mi][ji] + bias[d * G4H + j];
        }
}

// ---------------- LSTM recurrent step (float4 gate weights) ----------------
__global__ void lstm_step_kernel(float* __restrict__ Xout, int layer, int step)
{
    int b = blockIdx.x, d = blockIdx.y, tid = threadIdx.x;  // tid in [0,448)
    int t = (d == 0) ? step : (EM - 1 - step);
    __shared__ float hs[HM];
    int hidx = (d * BN_ + b) * HM + tid;
    hs[tid] = (step == 0) ? 0.f : g_h[hidx];
    __syncthreads();

    const float* W = g_W4 + ((size_t)layer * 2 + d) * HM * G4H;
    float a0 = 0.f, a1 = 0.f, a2 = 0.f, a3 = 0.f;
#pragma unroll 4
    for (int hp = 0; hp < HM; hp++) {
        float hv = hs[hp];
        float4 wv = ((const float4*)(W + (size_t)hp * G4H))[tid];
        a0 = fmaf(wv.x, hv, a0);
        a1 = fmaf(wv.y, hv, a1);
        a2 = fmaf(wv.z, hv, a2);
        a3 = fmaf(wv.w, hv, a3);
    }
    const float* gi = g_Gin + ((size_t)d * (BN_ * EM) + b * EM + t) * G4H + tid;
    a0 += gi[0 * HM]; a1 += gi[1 * HM]; a2 += gi[2 * HM]; a3 += gi[3 * HM];

    float cp = (step == 0) ? 0.f : g_cst[hidx];
    float si = 1.f / (1.f + expf(-a0));
    float sf = 1.f / (1.f + expf(-a1));
    float so = 1.f / (1.f + expf(-a3));
    float cn = sf * cp + si * tanhf(a2);
    float hn = so * tanhf(cn);
    g_cst[hidx] = cn;
    g_h[hidx] = hn;
    Xout[((size_t)b * EM + t) * CM + d * HM + tid] = hn;
}

// ---------------- w[b][k] = sum_c (zl+0.1*noise)[b][c] * P[b][c][k] --------
__global__ void w_kernel(const float* __restrict__ P,
                         const float* __restrict__ noise, int t)
{
    int b = blockIdx.y;
    int k = blockIdx.x * 256 + threadIdx.x;
    __shared__ float zn[CM];
    const float* zr = g_X2 + ((size_t)b * EM + t) * CM;
    const float* nr = noise + ((size_t)t * BN_ + b) * CM;
    for (int c = threadIdx.x; c < CM; c += 256)
        zn[c] = zr[c] + 0.1f * nr[c];
    __syncthreads();
    const float* Pb = P + (size_t)b * CM * KM + k;
    float acc = 0.f;
#pragma unroll 8
    for (int c = 0; c < CM; c++)
        acc = fmaf(zn[c], Pb[(size_t)c * KM], acc);
    g_w[b * KM + k] = acc;
}

// ------------- wU[b][j] = sum_k w[b][k]*cov[b][k][j] ----------------------
__global__ void wU_kernel(const float* __restrict__ cov)
{
    int b = blockIdx.y;
    int j = blockIdx.x * 256 + threadIdx.x;
    __shared__ float ws[KM];
    for (int i = threadIdx.x; i < KM; i += 256) ws[i] = g_w[b * KM + i];
    __syncthreads();
    const float* cb = cov + (size_t)b * KM * KM + j;
    float acc = 0.f;
#pragma unroll 8
    for (int k = 0; k < KM; k++)
        acc = fmaf(ws[k], cb[(size_t)k * KM], acc);
    g_wU[b * KM + j] = acc;
}

// ------------- sigma + c = clip(wU/sigma) per batch -----------------------
__global__ void sigma_c_kernel()
{
    int b = blockIdx.x, tid = threadIdx.x;   // 512 threads
    __shared__ float red[512];
    float wv = g_w[b * KM + tid];
    float wu = g_wU[b * KM + tid];
    red[tid] = wv * wu;
    __syncthreads();
    for (int s = 256; s > 0; s >>= 1) {
        if (tid < s) red[tid] += red[tid + s];
        __syncthreads();
    }
    __shared__ float s_sigma;
    if (tid == 0) s_sigma = fmaxf(red[0] + 0.01f, 1e-6f);
    __syncthreads();
    g_cc[b * KM + tid] = clampf(wu / s_sigma, -1000.f, 1000.f);
}

// ------------- fused: Delta[b][c] then mean column update -----------------
__global__ void deltaupd_kernel(float* __restrict__ mean, int t)
{
    int b = blockIdx.y;
    int c = blockIdx.x * 128 + threadIdx.x;
    __shared__ float ws[KM];
    __shared__ float cs[KM];
    for (int i = threadIdx.x; i < KM; i += 128) {
        ws[i] = g_w[b * KM + i];
        cs[i] = g_cc[b * KM + i];
    }
    __syncthreads();
    float* mb = mean + (size_t)b * KM * CM + c;
    float acc = 0.f;
#pragma unroll 8
    for (int k = 0; k < KM; k++)
        acc = fmaf(ws[k], mb[(size_t)k * CM], acc);
    float dv = clampf(g_X2[((size_t)b * EM + t) * CM + c] - acc, -100.f, 100.f);
#pragma unroll 4
    for (int k = 0; k < KM; k++) {
        float m = mb[(size_t)k * CM] + cs[k] * dv;
        mb[(size_t)k * CM] = clampf(m, -1000.f, 1000.f);
    }
}

// ------------- cov update (symmetrized rank-1 + diag clip + EPS) ----------
__global__ void cov_update_kernel(float* __restrict__ cov)
{
    int i = blockIdx.x, b = blockIdx.y;
    float ci = g_cc[b * KM + i];
    float wUi = g_wU[b * KM + i];
    size_t base = ((size_t)b * KM + i) * KM;
    for (int j = threadIdx.x; j < KM; j += 128) {
        float cj = g_cc[b * KM + j];
        float wUj = g_wU[b * KM + j];
        float v = cov[base + j] - 0.5f * (ci * wUj + cj * wUi);
        if (j == i) v = clampf(v, 0.001f, 1000.f) + 1e-6f;
        cov[base + j] = v;
    }
}

// ------------- KL partial per batch ---------------------------------------
__global__ void kl_partial_kernel(const float* __restrict__ mean,
                                  const float* __restrict__ cov,
                                  const float* __restrict__ mm)
{
    int b = blockIdx.x, tid = threadIdx.x;  // 256
    const float pd = 1.0f + 1e-6f;
    const float lpd = logf(pd);
    float s1 = 0.f, s4 = 0.f, s2 = 0.f;

    for (int k = tid; k < KM; k += 256) {
        float q = clampf(cov[((size_t)b * KM + k) * KM + k], 0.001f, 1e6f);
        s1 += clampf(q / pd, 1e-6f, 1000.f);
        s4 += clampf(lpd - logf(q), -10.f, 10.f);
    }
    const float* mb = mean + (size_t)b * KM * CM;
    for (int idx = tid; idx < KM * CM; idx += 256) {
        float d = mb[idx] - mm[idx];
        s2 += fminf(d * d, 1000.f);
    }
    s2 /= pd;

    __shared__ float r1[256], r2[256], r4[256];
    r1[tid] = s1; r2[tid] = s2; r4[tid] = s4;
    __syncthreads();
    for (int s = 128; s > 0; s >>= 1) {
        if (tid < s) { r1[tid] += r1[tid + s]; r2[tid] += r2[tid + s]; r4[tid] += r4[tid + s]; }
        __syncthreads();
    }
    if (tid == 0) {
        float t1 = clampf((float)CM * r1[0], -1e6f, 1e6f);
        float t2 = clampf(r2[0], -1e6f, 1e6f);
        float t4 = clampf((float)CM * r4[0], -1e6f, 1e6f);
        g_klp[b] = t1 + t2 + t4 - (float)(CM * KM);
    }
}

__global__ void kl_final_kernel(float* __restrict__ dkl)
{
    float s = 0.f;
    for (int b = 0; b < BN_; b++) s += g_klp[b];
    dkl[0] = s * (1.0f / BN_);
}

// =========================== host side ====================================
extern "C" void kernel_launch(void* const* d_in, const int* in_sizes, int n_in,
                              void* d_out, int out_size)
{
    const float* z    = (const float*)d_in[0];
    const float* mm   = (const float*)d_in[1];
    const float* nois = (const float*)d_in[2];
    const float* Wih0 = (const float*)d_in[3];
    const float* Whh0 = (const float*)d_in[4];
    const float* b0   = (const float*)d_in[5];
    const float* Wih1 = (const float*)d_in[6];
    const float* Whh1 = (const float*)d_in[7];
    const float* b1   = (const float*)d_in[8];

    float* out_mean = (float*)d_out;                               // (B,K,C)
    float* out_cov  = out_mean + (size_t)BN_ * KM * CM;            // (B,K,K)
    float* out_dkl  = out_cov + (size_t)BN_ * KM * KM;             // scalar

    float *pW4, *pX0, *pX1, *pX2, *pP1, *pP2;
    cudaGetSymbolAddress((void**)&pW4, g_W4);
    cudaGetSymbolAddress((void**)&pX0, g_X0);
    cudaGetSymbolAddress((void**)&pX1, g_X1);
    cudaGetSymbolAddress((void**)&pX2, g_X2);
    cudaGetSymbolAddress((void**)&pP1, g_P1);
    cudaGetSymbolAddress((void**)&pP2, g_P2);

    __nv_bfloat16 *pmH, *pmL, *pPAh, *pPAl, *pPBh, *pPBl, *pQH, *pQL;
    cudaGetSymbolAddress((void**)&pmH,  g_mH);
    cudaGetSymbolAddress((void**)&pmL,  g_mL);
    cudaGetSymbolAddress((void**)&pPAh, g_PAh);
    cudaGetSymbolAddress((void**)&pPAl, g_PAl);
    cudaGetSymbolAddress((void**)&pPBh, g_PBh);
    cudaGetSymbolAddress((void**)&pPBl, g_PBl);
    cudaGetSymbolAddress((void**)&pQH,  g_QH);
    cudaGetSymbolAddress((void**)&pQL,  g_QL);

    cudaFuncSetAttribute(gemm_mma_kernel,
                         cudaFuncAttributeMaxDynamicSharedMemorySize, GEMM_SMEM);

    // --- pre: weight repack; build X0; init mean/cov ---
    w4_transpose_kernel<<<dim3(14, 56, 2), dim3(32, 8)>>>(Whh0, pW4);
    w4_transpose_kernel<<<dim3(14, 56, 2), dim3(32, 8)>>>(
        Whh1, pW4 + (size_t)2 * HM * G4H);
    build_x0_kernel<<<(BN_ * EM * CM + 255) / 256, 256>>>(z);
    init_mean_kernel<<<dim3(KM * CM / 256, BN_), 256>>>(mm, out_mean);
    init_cov_kernel<<<dim3(KM * KM / 256, BN_), 256>>>(out_cov);

    // --- bidirectional 2-layer LSTM ---
    inproj_kernel<<<dim3(G4H / 64, 2), 256>>>(pX0, Wih0, b0);
    for (int s = 0; s < EM; s++)
        lstm_step_kernel<<<dim3(BN_, 2), HM>>>(pX1, 0, s);
    inproj_kernel<<<dim3(G4H / 64, 2), 256>>>(pX1, Wih1, b1);
    for (int s = 0; s < EM; s++)
        lstm_step_kernel<<<dim3(BN_, 2), HM>>>(pX2, 1, s);

    // --- episodic memory write loop ---
    for (int t = 0; t < EM; t++) {
        // mean -> meanH/L splits; P0 = alpha*mean^T (fp32 + splits), fused
        meansplit_p0_kernel<<<dim3(CM / 32, KM / 32, BN_), dim3(32, 8)>>>(
            out_mean, pmH, pmL, pP1, pPAh, pPAl);

        float* Pa = pP1;  float* Pb = pP2;
        __nv_bfloat16 *PaH = pPAh, *PaL = pPAl, *PbH = pPBh, *PbL = pPBl;
        for (int it = 0; it < 3; it++) {
            // Q = mean(512x896) @ Pa(896x512) -> QH/QL only (fused split)
            gemm_mma_kernel<<<dim3(KM / 128, KM / 128, BN_), 256, GEMM_SMEM>>>(
                pmH, pmL, PaH, PaL, nullptr, nullptr, pQH, pQL,
                KM, KM, CM, 0, 0, 1);
            // Pb = 2*Pa - Pa(896x512) @ Q(512x512) -> fp32 + splits
            gemm_mma_kernel<<<dim3(KM / 128, CM / 128, BN_), 256, GEMM_SMEM>>>(
                PaH, PaL, pQH, pQL, Pb, Pa, PbH, PbL,
                CM, KM, KM, 1, 1, (it < 2) ? 1 : 0);
            float* tf = Pa; Pa = Pb; Pb = tf;
            __nv_bfloat16* th = PaH; PaH = PbH; PbH = th;
            __nv_bfloat16* tl = PaL; PaL = PbL; PbL = tl;
        }
        // final P (fp32) is in Pa

        w_kernel<<<dim3(KM / 256, BN_), 256>>>(Pa, nois, t);
        wU_kernel<<<dim3(KM / 256, BN_), 256>>>(out_cov);
        sigma_c_kernel<<<BN_, KM>>>();
        deltaupd_kernel<<<dim3(CM / 128, BN_), 128>>>(out_mean, t);
        cov_update_kernel<<<dim3(KM, BN_), 128>>>(out_cov);
    }

    // --- KL ---
    kl_partial_kernel<<<BN_, 256>>>(out_mean, out_cov, mm);
    kl_final_kernel<<<1, 1>>>(out_dkl);
}